// round 13
// baseline (speedup 1.0000x reference)
#include <cuda_runtime.h>
#include <cuda_bf16.h>
#include <stdint.h>
#include <math.h>

#define T_SEQ  2048
#define NE     2048
#define NH     16
#define NG     4
#define HS     128
#define QKVD   3072
#define INTERD 5632
#define VOCABN 32000

typedef __nv_bfloat16 bf16;

// ---------------- scratch (device globals; no allocations) ----------------
__device__ __align__(256) float g_X[T_SEQ * NE];
__device__ __align__(256) float g_QKV[T_SEQ * QKVD];
__device__ __align__(256) float g_H1[T_SEQ * INTERD];
__device__ __align__(256) float g_H2[T_SEQ * INTERD];
__device__ __align__(256) float g_P[NG * T_SEQ * HS];     // prefix sums of K
__device__ __align__(256) float g_inv[NH * T_SEQ];        // 1/(rowsum+1e-8)

__device__ __align__(256) bf16 g_Nh[T_SEQ * NE],          g_Nl[T_SEQ * NE];
__device__ __align__(256) bf16 g_Wh[(size_t)VOCABN * NE], g_Wl[(size_t)VOCABN * NE];
__device__ __align__(256) bf16 g_Qh[NH * T_SEQ * HS],     g_Ql[NH * T_SEQ * HS];
__device__ __align__(256) bf16 g_Kh[NG * T_SEQ * HS],     g_Kl[NG * T_SEQ * HS];
__device__ __align__(256) bf16 g_Vh[NG * HS * T_SEQ],     g_Vl[NG * HS * T_SEQ];
__device__ __align__(256) bf16 g_Sh[(size_t)NH * T_SEQ * T_SEQ], g_Sl[(size_t)NH * T_SEQ * T_SEQ];
__device__ __align__(256) bf16 g_Yh[T_SEQ * NE],          g_Yl[T_SEQ * NE];
__device__ __align__(256) bf16 g_Hh[T_SEQ * INTERD],      g_Hl[T_SEQ * INTERD];

__device__ float g_cos[T_SEQ * 64];
__device__ float g_sin[T_SEQ * 64];

__device__ __forceinline__ void split2(float x, bf16& h, bf16& l) {
    h = __float2bfloat16_rn(x);
    l = __float2bfloat16_rn(x - __bfloat162float(h));
}
__device__ __forceinline__ uint32_t pack2(bf16 a, bf16 b) {
    return (uint32_t)__bfloat16_as_ushort(a) | ((uint32_t)__bfloat16_as_ushort(b) << 16);
}

// ================= split-bf16 tensor-core GEMM (mma.sync) =================
// C[z] = alpha * (Ah+Al)[z] @ (Bh+Bl)[z/bdiv]^T, fp32 accum.
// Output: fp32 C (+RES) or split-bf16 (Ch,Cl); optional per-row scale; optional
// causal block-skip + mask; optional K-limit to bm+128.
#define PAD 40
#define SA_H 0
#define SA_L 5120
#define SB_H 10240
#define SB_L 15360
#define STAGE_ELEMS 20480          // 4 * 128 * PAD
#define GEMM_SMEM (2 * STAGE_ELEMS * 2)   // 81920 bytes

#define LDSM4(R0,R1,R2,R3,ADDR) \
  asm volatile("ldmatrix.sync.aligned.m8n8.x4.shared.b16 {%0,%1,%2,%3}, [%4];" \
    : "=r"(R0),"=r"(R1),"=r"(R2),"=r"(R3) : "r"(ADDR))

#define MMA_B16(C,A,B) \
  asm volatile("mma.sync.aligned.m16n8k16.row.col.f32.bf16.bf16.f32 " \
    "{%0,%1,%2,%3},{%4,%5,%6,%7},{%8,%9},{%0,%1,%2,%3};" \
    : "+f"((C)[0]),"+f"((C)[1]),"+f"((C)[2]),"+f"((C)[3]) \
    : "r"((A)[0]),"r"((A)[1]),"r"((A)[2]),"r"((A)[3]),"r"((B)[0]),"r"((B)[1]))

__device__ __forceinline__ void cp16(bf16* s, const bf16* g) {
    uint32_t sa = (uint32_t)__cvta_generic_to_shared(s);
    asm volatile("cp.async.cg.shared.global [%0], [%1], 16;" :: "r"(sa), "l"(g));
}

__global__ __launch_bounds__(256, 1) void gemm_bf16s(
    const bf16* __restrict__ Ah, const bf16* __restrict__ Al,
    const bf16* __restrict__ Bh, const bf16* __restrict__ Bl,
    float* __restrict__ C, const float* __restrict__ RES,
    bf16* __restrict__ Ch, bf16* __restrict__ Cl,
    const float* __restrict__ rowscale_, long sRS,
    int causal, int limitk,
    int K, int lda, int ldb, int ldc, float alpha,
    long sA, long sB, long sC, int bdiv)
{
    extern __shared__ bf16 sm[];
    int bm = blockIdx.y * 128, bn = blockIdx.x * 128;
    if (causal && bn > bm) return;          // fully-masked tile

    int z = blockIdx.z;
    Ah += (long)z * sA;  Al += (long)z * sA;
    Bh += (long)(z / bdiv) * sB;  Bl += (long)(z / bdiv) * sB;
    if (C)   C   += (long)z * sC;
    if (RES) RES += (long)z * sC;
    if (Ch)  { Ch += (long)z * sC; Cl += (long)z * sC; }
    const float* rowscale = rowscale_ ? rowscale_ + (long)z * sRS : nullptr;

    int tid = threadIdx.x;

    // gmem->smem copy layout: 2 threads per row, 16 bf16 each
    int lrow = tid >> 1;
    int lch  = (tid & 1) << 4;
    const bf16* gAh = Ah + (long)(bm + lrow) * lda + lch;
    const bf16* gAl = Al + (long)(bm + lrow) * lda + lch;
    const bf16* gBh = Bh + (long)(bn + lrow) * ldb + lch;
    const bf16* gBl = Bl + (long)(bn + lrow) * ldb + lch;
    int soff = lrow * PAD + lch;

    int lane = tid & 31, wid = tid >> 5;
    int wm = wid >> 2, wn = wid & 3;

    int a_row = wm * 64 + (lane & 15);
    int a_col = (lane >> 4) << 3;
    int b_row = wn * 32 + (lane & 7) + ((lane >> 4) << 3);
    int b_col = lane & 8;

    float c[4][4][4];
#pragma unroll
    for (int i = 0; i < 4; i++)
#pragma unroll
        for (int j = 0; j < 4; j++)
#pragma unroll
            for (int e = 0; e < 4; e++) c[i][j][e] = 0.f;

    int Keff = limitk ? (bm + 128 < K ? bm + 128 : K) : K;
    int nk = Keff >> 5;

    // prefetch stage 0
    {
        bf16* s = sm + soff;
        cp16(s + SA_H, gAh); cp16(s + SA_H + 8, gAh + 8);
        cp16(s + SA_L, gAl); cp16(s + SA_L + 8, gAl + 8);
        cp16(s + SB_H, gBh); cp16(s + SB_H + 8, gBh + 8);
        cp16(s + SB_L, gBl); cp16(s + SB_L + 8, gBl + 8);
    }
    asm volatile("cp.async.commit_group;");

    for (int kt = 0; kt < nk; kt++) {
        if (kt + 1 < nk) {
            int k0 = (kt + 1) << 5;
            bf16* s = sm + ((kt + 1) & 1) * STAGE_ELEMS + soff;
            cp16(s + SA_H, gAh + k0); cp16(s + SA_H + 8, gAh + k0 + 8);
            cp16(s + SA_L, gAl + k0); cp16(s + SA_L + 8, gAl + k0 + 8);
            cp16(s + SB_H, gBh + k0); cp16(s + SB_H + 8, gBh + k0 + 8);
            cp16(s + SB_L, gBl + k0); cp16(s + SB_L + 8, gBl + k0 + 8);
            asm volatile("cp.async.commit_group;");
            asm volatile("cp.async.wait_group 1;");
        } else {
            asm volatile("cp.async.wait_group 0;");
        }
        __syncthreads();

        uint32_t base = (uint32_t)__cvta_generic_to_shared(sm + (kt & 1) * STAGE_ELEMS);
#pragma unroll
        for (int ks = 0; ks < 2; ks++) {
            int kf = ks << 4;
            uint32_t ah[4][4], al[4][4], bh[4][2], bl[4][2];
#pragma unroll
            for (int mi = 0; mi < 4; mi++) {
                uint32_t ad = base + (uint32_t)(((a_row + mi * 16) * PAD + kf + a_col) * 2);
                LDSM4(ah[mi][0], ah[mi][1], ah[mi][2], ah[mi][3], ad + SA_H * 2);
                LDSM4(al[mi][0], al[mi][1], al[mi][2], al[mi][3], ad + SA_L * 2);
            }
#pragma unroll
            for (int nj = 0; nj < 2; nj++) {
                uint32_t bd = base + (uint32_t)(((b_row + nj * 16) * PAD + kf + b_col) * 2);
                uint32_t r0, r1, r2, r3;
                LDSM4(r0, r1, r2, r3, bd + SB_H * 2);
                bh[nj*2][0] = r0; bh[nj*2][1] = r1; bh[nj*2+1][0] = r2; bh[nj*2+1][1] = r3;
                LDSM4(r0, r1, r2, r3, bd + SB_L * 2);
                bl[nj*2][0] = r0; bl[nj*2][1] = r1; bl[nj*2+1][0] = r2; bl[nj*2+1][1] = r3;
            }
#pragma unroll
            for (int mi = 0; mi < 4; mi++)
#pragma unroll
                for (int ni = 0; ni < 4; ni++) {
                    MMA_B16(c[mi][ni], ah[mi], bh[ni]);
                    MMA_B16(c[mi][ni], ah[mi], bl[ni]);
                    MMA_B16(c[mi][ni], al[mi], bh[ni]);
                }
        }
        __syncthreads();
    }

    // epilogue
    int g4 = lane >> 2, t4 = lane & 3;
#pragma unroll
    for (int mi = 0; mi < 4; mi++) {
        long r0 = bm + wm * 64 + mi * 16 + g4;
        long r1 = r0 + 8;
        float s0 = rowscale ? rowscale[r0] : 1.f;
        float s1 = rowscale ? rowscale[r1] : 1.f;
#pragma unroll
        for (int ni = 0; ni < 4; ni++) {
            long col = bn + wn * 32 + ni * 8 + t4 * 2;
            float v00 = c[mi][ni][0] * alpha * s0;
            float v01 = c[mi][ni][1] * alpha * s0;
            float v10 = c[mi][ni][2] * alpha * s1;
            float v11 = c[mi][ni][3] * alpha * s1;
            if (causal) {
                if (col     > r0) v00 = 0.f;
                if (col + 1 > r0) v01 = 0.f;
                if (col     > r1) v10 = 0.f;
                if (col + 1 > r1) v11 = 0.f;
            }
            if (Ch) {
                bf16 h0, l0, h1, l1;
                split2(v00, h0, l0); split2(v01, h1, l1);
                *(uint32_t*)(Ch + r0 * ldc + col) = pack2(h0, h1);
                *(uint32_t*)(Cl + r0 * ldc + col) = pack2(l0, l1);
                split2(v10, h0, l0); split2(v11, h1, l1);
                *(uint32_t*)(Ch + r1 * ldc + col) = pack2(h0, h1);
                *(uint32_t*)(Cl + r1 * ldc + col) = pack2(l0, l1);
            } else {
                float2 v0, v1;
                v0.x = v00; v0.y = v01; v1.x = v10; v1.y = v11;
                if (RES) {
                    float2 q0 = *(const float2*)(RES + r0 * ldc + col);
                    float2 q1 = *(const float2*)(RES + r1 * ldc + col);
                    v0.x += q0.x; v0.y += q0.y; v1.x += q1.x; v1.y += q1.y;
                }
                *(float2*)(C + r0 * ldc + col) = v0;
                *(float2*)(C + r1 * ldc + col) = v1;
            }
        }
    }
}

// ---------------- pointwise kernels ----------------
__global__ void split_k(const float* __restrict__ X, bf16* __restrict__ H,
                        bf16* __restrict__ L, long n)
{
    long i = ((long)blockIdx.x * 256 + threadIdx.x) * 4;
    if (i < n) {
        float4 v = *(const float4*)(X + i);
        bf16 h0, h1, h2, h3, l0, l1, l2, l3;
        split2(v.x, h0, l0); split2(v.y, h1, l1);
        split2(v.z, h2, l2); split2(v.w, h3, l3);
        uint2 hv; hv.x = pack2(h0, h1); hv.y = pack2(h2, h3);
        uint2 lv; lv.x = pack2(l0, l1); lv.y = pack2(l2, l3);
        *(uint2*)(H + i) = hv;
        *(uint2*)(L + i) = lv;
    }
}

__global__ void embed_k(const int* __restrict__ idx, const float* __restrict__ wte,
                        float* __restrict__ X)
{
    int t = blockIdx.x;
    int tok = idx[t];
    const float* src = wte + (long)tok * NE;
    for (int i = threadIdx.x; i < NE; i += 256)
        X[(long)t * NE + i] = src[i];
}

__global__ void rmsnorm_k(const float* __restrict__ X, const float* __restrict__ w,
                          bf16* __restrict__ H, bf16* __restrict__ L)
{
    int t = blockIdx.x;
    const float* x = X + (long)t * NE;
    float ss = 0.f;
    for (int i = threadIdx.x; i < NE; i += 256) { float v = x[i]; ss += v * v; }
    __shared__ float red[256];
    red[threadIdx.x] = ss; __syncthreads();
    for (int s = 128; s > 0; s >>= 1) {
        if (threadIdx.x < s) red[threadIdx.x] += red[threadIdx.x + s];
        __syncthreads();
    }
    float r = rsqrtf(red[0] / NE + 1e-5f);
    for (int i = threadIdx.x; i < NE; i += 256) {
        bf16 h, l; split2(x[i] * r * w[i], h, l);
        H[(long)t * NE + i] = h;
        L[(long)t * NE + i] = l;
    }
}

__global__ void rope_tab_k()
{
    int t = blockIdx.x, d = threadIdx.x;
    double theta = exp(-(double)d * (9.210340371976184 / 64.0));
    double a = (double)t * theta;
    g_cos[t * 64 + d] = (float)cos(a);
    g_sin[t * 64 + d] = (float)sin(a);
}

__global__ void rope_elu_k(const float* __restrict__ QKV,
                           bf16* __restrict__ Qh, bf16* __restrict__ Ql,
                           bf16* __restrict__ Kh, bf16* __restrict__ Kl)
{
    int t = blockIdx.x;
    int u = blockIdx.y;
    int d = threadIdx.x;
    int gidx, slot;
    long off;
    bf16 *oh, *ol;
    if (u < NH) { gidx = u >> 2; slot = u & 3; off = ((long)u * T_SEQ + t) * HS; oh = Qh; ol = Ql; }
    else        { gidx = u - NH; slot = 4;     off = ((long)gidx * T_SEQ + t) * HS; oh = Kh; ol = Kl; }
    const float* src = QKV + (long)t * QKVD + (gidx * 6 + slot) * HS;
    float x1 = src[d], x2 = src[d + 64];
    float cc = g_cos[t * 64 + d], ss = g_sin[t * 64 + d];
    float o1 = x1 * cc - x2 * ss;
    float o2 = x1 * ss + x2 * cc;
    float e1 = (o1 > 0.f) ? o1 + 1.f : expf(o1);
    float e2 = (o2 > 0.f) ? o2 + 1.f : expf(o2);
    bf16 h, l;
    split2(e1, h, l); oh[off + d] = h;      ol[off + d] = l;
    split2(e2, h, l); oh[off + d + 64] = h; ol[off + d + 64] = l;
}

__global__ void copy_v_k(const float* __restrict__ QKV,
                         bf16* __restrict__ Vh, bf16* __restrict__ Vl)
{
    int t = blockIdx.x, g = blockIdx.y, d = threadIdx.x;
    float v = QKV[(long)t * QKVD + (g * 6 + 5) * HS + d];
    bf16 h, l; split2(v, h, l);
    long o = ((long)g * HS + d) * T_SEQ + t;
    Vh[o] = h; Vl[o] = l;
}

// prefix sums of K over time: P[g][t][d] = sum_{s<=t} K[g][s][d]
__global__ void prefix_k()
{
    int g = blockIdx.x;
    int d = blockIdx.y * 32 + threadIdx.x;
    float acc = 0.f;
    for (int t = 0; t < T_SEQ; t++) {
        long o = ((long)g * T_SEQ + t) * HS + d;
        acc += __bfloat162float(g_Kh[o]) + __bfloat162float(g_Kl[o]);
        g_P[o] = acc;
    }
}

// inv rowsum: 1 / (scale * q[h][t] . P[g][t] + 1e-8)
__global__ void rowsum_k()
{
    int t = blockIdx.x, h = blockIdx.y, g = h >> 2;
    int lane = threadIdx.x;
    long qo = ((long)h * T_SEQ + t) * HS;
    long po = ((long)g * T_SEQ + t) * HS;
    float acc = 0.f;
#pragma unroll
    for (int j = 0; j < 4; j++) {
        int d = lane + j * 32;
        float q = __bfloat162float(g_Qh[qo + d]) + __bfloat162float(g_Ql[qo + d]);
        acc += q * g_P[po + d];
    }
#pragma unroll
    for (int s = 16; s > 0; s >>= 1)
        acc += __shfl_xor_sync(0xFFFFFFFF, acc, s);
    if (lane == 0) {
        const float scale = 0.088388347648318447f;   // 1/sqrt(128)
        g_inv[(long)h * T_SEQ + t] = 1.f / (scale * acc + 1e-8f);
    }
}

__global__ void silu_mul_k(const float* __restrict__ H1, const float* __restrict__ H2,
                           bf16* __restrict__ Hh, bf16* __restrict__ Hl)
{
    long i = (long)blockIdx.x * 256 + threadIdx.x;
    if (i < (long)T_SEQ * INTERD) {
        float a = H1[i];
        float v = (a / (1.f + expf(-a))) * H2[i];
        bf16 h, l; split2(v, h, l);
        Hh[i] = h; Hl[i] = l;
    }
}

// ---------------- driver ----------------
static void launch_gemm_f32(const bf16* Ah, const bf16* Al, const bf16* Bh, const bf16* Bl,
                            float* C, const float* RES, int M, int N, int K,
                            int lda, int ldb, int ldc, float alpha,
                            long sA, long sB, long sC, int bdiv, int Z)
{
    gemm_bf16s<<<dim3(N / 128, M / 128, Z), 256, GEMM_SMEM>>>(
        Ah, Al, Bh, Bl, C, RES, nullptr, nullptr, nullptr, 0, 0, 0,
        K, lda, ldb, ldc, alpha, sA, sB, sC, bdiv);
}

static void launch_split(const float* X, bf16* H, bf16* L, long n)
{
    split_k<<<(int)((n + 1023) / 1024), 256>>>(X, H, L, n);
}

extern "C" void kernel_launch(void* const* d_in, const int* in_sizes, int n_in,
                              void* d_out, int out_size)
{
    const int*   idx      = (const int*)d_in[0];
    const float* wte      = (const float*)d_in[1];
    const float* attn_w   = (const float*)d_in[2];
    const float* proj_w   = (const float*)d_in[3];
    const float* w1       = (const float*)d_in[4];
    const float* w2       = (const float*)d_in[5];
    const float* w3       = (const float*)d_in[6];
    const float* norm1_w  = (const float*)d_in[7];
    const float* norm2_w  = (const float*)d_in[8];
    const float* ln_f_w   = (const float*)d_in[9];
    const float* lm_head  = (const float*)d_in[10];
    float* out = (float*)d_out;

    cudaFuncSetAttribute(gemm_bf16s, cudaFuncAttributeMaxDynamicSharedMemorySize, GEMM_SMEM);

    float *X, *QKV, *H1, *H2, *INV;
    bf16 *Nh, *Nl, *Wh, *Wl, *Qh, *Ql, *Kh, *Kl, *Vh, *Vl, *Sh, *Sl, *Yh, *Yl, *Hh, *Hl;
    cudaGetSymbolAddress((void**)&X,   g_X);
    cudaGetSymbolAddress((void**)&QKV, g_QKV);
    cudaGetSymbolAddress((void**)&H1,  g_H1);
    cudaGetSymbolAddress((void**)&H2,  g_H2);
    cudaGetSymbolAddress((void**)&INV, g_inv);
    cudaGetSymbolAddress((void**)&Nh,  g_Nh); cudaGetSymbolAddress((void**)&Nl, g_Nl);
    cudaGetSymbolAddress((void**)&Wh,  g_Wh); cudaGetSymbolAddress((void**)&Wl, g_Wl);
    cudaGetSymbolAddress((void**)&Qh,  g_Qh); cudaGetSymbolAddress((void**)&Ql, g_Ql);
    cudaGetSymbolAddress((void**)&Kh,  g_Kh); cudaGetSymbolAddress((void**)&Kl, g_Kl);
    cudaGetSymbolAddress((void**)&Vh,  g_Vh); cudaGetSymbolAddress((void**)&Vl, g_Vl);
    cudaGetSymbolAddress((void**)&Sh,  g_Sh); cudaGetSymbolAddress((void**)&Sl, g_Sl);
    cudaGetSymbolAddress((void**)&Yh,  g_Yh); cudaGetSymbolAddress((void**)&Yl, g_Yl);
    cudaGetSymbolAddress((void**)&Hh,  g_Hh); cudaGetSymbolAddress((void**)&Hl, g_Hl);

    const float scale = 1.f / sqrtf((float)HS);

    embed_k<<<T_SEQ, 256>>>(idx, wte, X);
    rope_tab_k<<<T_SEQ, 64>>>();

    for (int l = 0; l < 2; l++) {
        rmsnorm_k<<<T_SEQ, 256>>>(X, norm1_w + (long)l * NE, Nh, Nl);

        // qkv = n1 @ attn_w^T  (fp32 out)
        launch_split(attn_w + (long)l * QKVD * NE, Wh, Wl, (long)QKVD * NE);
        launch_gemm_f32(Nh, Nl, Wh, Wl, QKV, nullptr, T_SEQ, QKVD, NE,
                        NE, NE, QKVD, 1.f, 0, 0, 0, 1, 1);

        rope_elu_k<<<dim3(T_SEQ, NH + NG), 64>>>(QKV, Qh, Ql, Kh, Kl);
        copy_v_k<<<dim3(T_SEQ, NG), 128>>>(QKV, Vh, Vl);
        prefix_k<<<dim3(NG, HS / 32), 32>>>();
        rowsum_k<<<dim3(T_SEQ, NH), 32>>>();

        // S[h] = scale * Q[h] @ K[h/4]^T  -> masked split-bf16, causal block skip
        gemm_bf16s<<<dim3(T_SEQ / 128, T_SEQ / 128, NH), 256, GEMM_SMEM>>>(
            Qh, Ql, Kh, Kl, nullptr, nullptr, Sh, Sl, nullptr, 0,
            /*causal=*/1, /*limitk=*/0,
            HS, HS, HS, T_SEQ, scale,
            (long)T_SEQ * HS, (long)T_SEQ * HS, (long)T_SEQ * T_SEQ, 4);

        // Y[:, h*128:(h+1)*128] = inv[h] * (S[h] @ Vt[h/4]^T) -> split-bf16, K-limited
        gemm_bf16s<<<dim3(1, T_SEQ / 128, NH), 256, GEMM_SMEM>>>(
            Sh, Sl, Vh, Vl, nullptr, nullptr, Yh, Yl, INV, (long)T_SEQ,
            /*causal=*/0, /*limitk=*/1,
            T_SEQ, T_SEQ, T_SEQ, NE, 1.f,
            (long)T_SEQ * T_SEQ, (long)HS * T_SEQ, (long)HS, 4);

        // X += Y @ proj^T
        launch_split(proj_w + (long)l * NE * NE, Wh, Wl, (long)NE * NE);
        launch_gemm_f32(Yh, Yl, Wh, Wl, X, X, T_SEQ, NE, NE,
                        NE, NE, NE, 1.f, 0, 0, 0, 1, 1);

        rmsnorm_k<<<T_SEQ, 256>>>(X, norm2_w + (long)l * NE, Nh, Nl);

        launch_split(w1 + (long)l * INTERD * NE, Wh, Wl, (long)INTERD * NE);
        launch_gemm_f32(Nh, Nl, Wh, Wl, H1, nullptr, T_SEQ, INTERD, NE,
                        NE, NE, INTERD, 1.f, 0, 0, 0, 1, 1);
        launch_split(w2 + (long)l * INTERD * NE, Wh, Wl, (long)INTERD * NE);
        launch_gemm_f32(Nh, Nl, Wh, Wl, H2, nullptr, T_SEQ, INTERD, NE,
                        NE, NE, INTERD, 1.f, 0, 0, 0, 1, 1);

        silu_mul_k<<<(int)(((long)T_SEQ * INTERD + 255) / 256), 256>>>(H1, H2, Hh, Hl);

        // X += H @ w3^T
        launch_split(w3 + (long)l * NE * INTERD, Wh, Wl, (long)NE * INTERD);
        launch_gemm_f32(Hh, Hl, Wh, Wl, X, X, T_SEQ, NE, INTERD,
                        INTERD, INTERD, NE, 1.f, 0, 0, 0, 1, 1);
    }

    rmsnorm_k<<<T_SEQ, 256>>>(X, ln_f_w, Nh, Nl);

    // logits = x @ lm_head^T
    launch_split(lm_head, Wh, Wl, (long)VOCABN * NE);
    launch_gemm_f32(Nh, Nl, Wh, Wl, out, nullptr, T_SEQ, VOCABN, NE,
                    NE, NE, VOCABN, 1.f, 0, 0, 0, 1, 1);
}

// round 15
// speedup vs baseline: 1.1209x; 1.1209x over previous
#include <cuda_runtime.h>
#include <cuda_bf16.h>
#include <stdint.h>
#include <math.h>

#define T_SEQ  2048
#define NE     2048
#define NH     16
#define NG     4
#define HS     128
#define QKVD   3072
#define INTERD 5632
#define VOCABN 32000

typedef __nv_bfloat16 bf16;

// ---------------- scratch (device globals; no allocations) ----------------
__device__ __align__(256) float g_X[T_SEQ * NE];
__device__ __align__(256) float g_QKV[T_SEQ * QKVD];
__device__ __align__(256) float g_H1[T_SEQ * INTERD];
__device__ __align__(256) float g_H2[T_SEQ * INTERD];
__device__ __align__(256) float g_inv[NH * T_SEQ];        // 1/(rowsum+1e-8)

__device__ __align__(256) bf16 g_Nh[T_SEQ * NE],          g_Nl[T_SEQ * NE];
__device__ __align__(256) bf16 g_Wh[(size_t)VOCABN * NE], g_Wl[(size_t)VOCABN * NE];
__device__ __align__(256) bf16 g_Qh[NH * T_SEQ * HS],     g_Ql[NH * T_SEQ * HS];
__device__ __align__(256) bf16 g_Kh[NG * T_SEQ * HS],     g_Kl[NG * T_SEQ * HS];
__device__ __align__(256) bf16 g_Vh[NG * HS * T_SEQ],     g_Vl[NG * HS * T_SEQ];
__device__ __align__(256) bf16 g_Sh[(size_t)NH * T_SEQ * T_SEQ], g_Sl[(size_t)NH * T_SEQ * T_SEQ];
__device__ __align__(256) bf16 g_Yh[T_SEQ * NE],          g_Yl[T_SEQ * NE];
__device__ __align__(256) bf16 g_Hh[T_SEQ * INTERD],      g_Hl[T_SEQ * INTERD];

__device__ float g_cos[T_SEQ * 64];
__device__ float g_sin[T_SEQ * 64];

__device__ __forceinline__ void split2(float x, bf16& h, bf16& l) {
    h = __float2bfloat16_rn(x);
    l = __float2bfloat16_rn(x - __bfloat162float(h));
}
__device__ __forceinline__ uint32_t pack2(bf16 a, bf16 b) {
    return (uint32_t)__bfloat16_as_ushort(a) | ((uint32_t)__bfloat16_as_ushort(b) << 16);
}

// ================= split-bf16 tensor-core GEMM (mma.sync) =================
// C[z] = alpha * (Ah+Al)[z] @ (Bh+Bl)[z/bdiv]^T, fp32 accum.
// Output: fp32 C (+RES) or split-bf16 (Ch,Cl); optional per-row scale; optional
// causal block-skip + mask; optional K-limit to bm+128.
#define PAD 40
#define SA_H 0
#define SA_L 5120
#define SB_H 10240
#define SB_L 15360
#define STAGE_ELEMS 20480          // 4 * 128 * PAD
#define GEMM_SMEM (2 * STAGE_ELEMS * 2)   // 81920 bytes

#define LDSM4(R0,R1,R2,R3,ADDR) \
  asm volatile("ldmatrix.sync.aligned.m8n8.x4.shared.b16 {%0,%1,%2,%3}, [%4];" \
    : "=r"(R0),"=r"(R1),"=r"(R2),"=r"(R3) : "r"(ADDR))

#define MMA_B16(C,A,B) \
  asm volatile("mma.sync.aligned.m16n8k16.row.col.f32.bf16.bf16.f32 " \
    "{%0,%1,%2,%3},{%4,%5,%6,%7},{%8,%9},{%0,%1,%2,%3};" \
    : "+f"((C)[0]),"+f"((C)[1]),"+f"((C)[2]),"+f"((C)[3]) \
    : "r"((A)[0]),"r"((A)[1]),"r"((A)[2]),"r"((A)[3]),"r"((B)[0]),"r"((B)[1]))

__device__ __forceinline__ void cp16(bf16* s, const bf16* g) {
    uint32_t sa = (uint32_t)__cvta_generic_to_shared(s);
    asm volatile("cp.async.cg.shared.global [%0], [%1], 16;" :: "r"(sa), "l"(g));
}

__global__ __launch_bounds__(256, 1) void gemm_bf16s(
    const bf16* __restrict__ Ah, const bf16* __restrict__ Al,
    const bf16* __restrict__ Bh, const bf16* __restrict__ Bl,
    float* __restrict__ C, const float* __restrict__ RES,
    bf16* __restrict__ Ch, bf16* __restrict__ Cl,
    const float* __restrict__ rowscale_, long sRS,
    int causal, int limitk,
    int K, int lda, int ldb, int ldc, float alpha,
    long sA, long sB, long sC, int bdiv)
{
    extern __shared__ bf16 sm[];
    int bm = blockIdx.y * 128, bn = blockIdx.x * 128;
    if (causal && bn > bm) return;          // fully-masked tile

    int z = blockIdx.z;
    Ah += (long)z * sA;  Al += (long)z * sA;
    Bh += (long)(z / bdiv) * sB;  Bl += (long)(z / bdiv) * sB;
    if (C)   C   += (long)z * sC;
    if (RES) RES += (long)z * sC;
    if (Ch)  { Ch += (long)z * sC; Cl += (long)z * sC; }
    const float* rowscale = rowscale_ ? rowscale_ + (long)z * sRS : nullptr;

    int tid = threadIdx.x;

    // gmem->smem copy layout: 2 threads per row, 16 bf16 each
    int lrow = tid >> 1;
    int lch  = (tid & 1) << 4;
    const bf16* gAh = Ah + (long)(bm + lrow) * lda + lch;
    const bf16* gAl = Al + (long)(bm + lrow) * lda + lch;
    const bf16* gBh = Bh + (long)(bn + lrow) * ldb + lch;
    const bf16* gBl = Bl + (long)(bn + lrow) * ldb + lch;
    int soff = lrow * PAD + lch;

    int lane = tid & 31, wid = tid >> 5;
    int wm = wid >> 2, wn = wid & 3;

    int a_row = wm * 64 + (lane & 15);
    int a_col = (lane >> 4) << 3;
    int b_row = wn * 32 + (lane & 7) + ((lane >> 4) << 3);
    int b_col = lane & 8;

    float c[4][4][4];
#pragma unroll
    for (int i = 0; i < 4; i++)
#pragma unroll
        for (int j = 0; j < 4; j++)
#pragma unroll
            for (int e = 0; e < 4; e++) c[i][j][e] = 0.f;

    int Keff = limitk ? (bm + 128 < K ? bm + 128 : K) : K;
    int nk = Keff >> 5;

    // prefetch stage 0
    {
        bf16* s = sm + soff;
        cp16(s + SA_H, gAh); cp16(s + SA_H + 8, gAh + 8);
        cp16(s + SA_L, gAl); cp16(s + SA_L + 8, gAl + 8);
        cp16(s + SB_H, gBh); cp16(s + SB_H + 8, gBh + 8);
        cp16(s + SB_L, gBl); cp16(s + SB_L + 8, gBl + 8);
    }
    asm volatile("cp.async.commit_group;");

    for (int kt = 0; kt < nk; kt++) {
        if (kt + 1 < nk) {
            int k0 = (kt + 1) << 5;
            bf16* s = sm + ((kt + 1) & 1) * STAGE_ELEMS + soff;
            cp16(s + SA_H, gAh + k0); cp16(s + SA_H + 8, gAh + k0 + 8);
            cp16(s + SA_L, gAl + k0); cp16(s + SA_L + 8, gAl + k0 + 8);
            cp16(s + SB_H, gBh + k0); cp16(s + SB_H + 8, gBh + k0 + 8);
            cp16(s + SB_L, gBl + k0); cp16(s + SB_L + 8, gBl + k0 + 8);
            asm volatile("cp.async.commit_group;");
            asm volatile("cp.async.wait_group 1;");
        } else {
            asm volatile("cp.async.wait_group 0;");
        }
        __syncthreads();

        uint32_t base = (uint32_t)__cvta_generic_to_shared(sm + (kt & 1) * STAGE_ELEMS);
#pragma unroll
        for (int ks = 0; ks < 2; ks++) {
            int kf = ks << 4;
            uint32_t ah[4][4], al[4][4], bh[4][2], bl[4][2];
#pragma unroll
            for (int mi = 0; mi < 4; mi++) {
                uint32_t ad = base + (uint32_t)(((a_row + mi * 16) * PAD + kf + a_col) * 2);
                LDSM4(ah[mi][0], ah[mi][1], ah[mi][2], ah[mi][3], ad + SA_H * 2);
                LDSM4(al[mi][0], al[mi][1], al[mi][2], al[mi][3], ad + SA_L * 2);
            }
#pragma unroll
            for (int nj = 0; nj < 2; nj++) {
                uint32_t bd = base + (uint32_t)(((b_row + nj * 16) * PAD + kf + b_col) * 2);
                uint32_t r0, r1, r2, r3;
                LDSM4(r0, r1, r2, r3, bd + SB_H * 2);
                bh[nj*2][0] = r0; bh[nj*2][1] = r1; bh[nj*2+1][0] = r2; bh[nj*2+1][1] = r3;
                LDSM4(r0, r1, r2, r3, bd + SB_L * 2);
                bl[nj*2][0] = r0; bl[nj*2][1] = r1; bl[nj*2+1][0] = r2; bl[nj*2+1][1] = r3;
            }
#pragma unroll
            for (int mi = 0; mi < 4; mi++)
#pragma unroll
                for (int ni = 0; ni < 4; ni++) {
                    MMA_B16(c[mi][ni], ah[mi], bh[ni]);
                    MMA_B16(c[mi][ni], ah[mi], bl[ni]);
                    MMA_B16(c[mi][ni], al[mi], bh[ni]);
                }
        }
        __syncthreads();
    }

    // epilogue
    int g4 = lane >> 2, t4 = lane & 3;
#pragma unroll
    for (int mi = 0; mi < 4; mi++) {
        long r0 = bm + wm * 64 + mi * 16 + g4;
        long r1 = r0 + 8;
        float s0 = rowscale ? rowscale[r0] : 1.f;
        float s1 = rowscale ? rowscale[r1] : 1.f;
#pragma unroll
        for (int ni = 0; ni < 4; ni++) {
            long col = bn + wn * 32 + ni * 8 + t4 * 2;
            float v00 = c[mi][ni][0] * alpha * s0;
            float v01 = c[mi][ni][1] * alpha * s0;
            float v10 = c[mi][ni][2] * alpha * s1;
            float v11 = c[mi][ni][3] * alpha * s1;
            if (causal) {
                if (col     > r0) v00 = 0.f;
                if (col + 1 > r0) v01 = 0.f;
                if (col     > r1) v10 = 0.f;
                if (col + 1 > r1) v11 = 0.f;
            }
            if (Ch) {
                bf16 h0, l0, h1, l1;
                split2(v00, h0, l0); split2(v01, h1, l1);
                *(uint32_t*)(Ch + r0 * ldc + col) = pack2(h0, h1);
                *(uint32_t*)(Cl + r0 * ldc + col) = pack2(l0, l1);
                split2(v10, h0, l0); split2(v11, h1, l1);
                *(uint32_t*)(Ch + r1 * ldc + col) = pack2(h0, h1);
                *(uint32_t*)(Cl + r1 * ldc + col) = pack2(l0, l1);
            } else {
                float2 v0, v1;
                v0.x = v00; v0.y = v01; v1.x = v10; v1.y = v11;
                if (RES) {
                    float2 q0 = *(const float2*)(RES + r0 * ldc + col);
                    float2 q1 = *(const float2*)(RES + r1 * ldc + col);
                    v0.x += q0.x; v0.y += q0.y; v1.x += q1.x; v1.y += q1.y;
                }
                *(float2*)(C + r0 * ldc + col) = v0;
                *(float2*)(C + r1 * ldc + col) = v1;
            }
        }
    }
}

// ---------------- pointwise kernels ----------------
__global__ void split_k(const float* __restrict__ X, bf16* __restrict__ H,
                        bf16* __restrict__ L, long n)
{
    long i = ((long)blockIdx.x * 256 + threadIdx.x) * 4;
    if (i < n) {
        float4 v = *(const float4*)(X + i);
        bf16 h0, h1, h2, h3, l0, l1, l2, l3;
        split2(v.x, h0, l0); split2(v.y, h1, l1);
        split2(v.z, h2, l2); split2(v.w, h3, l3);
        uint2 hv; hv.x = pack2(h0, h1); hv.y = pack2(h2, h3);
        uint2 lv; lv.x = pack2(l0, l1); lv.y = pack2(l2, l3);
        *(uint2*)(H + i) = hv;
        *(uint2*)(L + i) = lv;
    }
}

__global__ void embed_k(const int* __restrict__ idx, const float* __restrict__ wte,
                        float* __restrict__ X)
{
    int t = blockIdx.x;
    int tok = idx[t];
    const float* src = wte + (long)tok * NE;
    for (int i = threadIdx.x; i < NE; i += 256)
        X[(long)t * NE + i] = src[i];
}

__global__ void rmsnorm_k(const float* __restrict__ X, const float* __restrict__ w,
                          bf16* __restrict__ H, bf16* __restrict__ L)
{
    int t = blockIdx.x;
    const float* x = X + (long)t * NE;
    float ss = 0.f;
    for (int i = threadIdx.x; i < NE; i += 256) { float v = x[i]; ss += v * v; }
    __shared__ float red[256];
    red[threadIdx.x] = ss; __syncthreads();
    for (int s = 128; s > 0; s >>= 1) {
        if (threadIdx.x < s) red[threadIdx.x] += red[threadIdx.x + s];
        __syncthreads();
    }
    float r = rsqrtf(red[0] / NE + 1e-5f);
    for (int i = threadIdx.x; i < NE; i += 256) {
        bf16 h, l; split2(x[i] * r * w[i], h, l);
        H[(long)t * NE + i] = h;
        L[(long)t * NE + i] = l;
    }
}

__global__ void rope_tab_k()
{
    int t = blockIdx.x, d = threadIdx.x;
    double theta = exp(-(double)d * (9.210340371976184 / 64.0));
    double a = (double)t * theta;
    g_cos[t * 64 + d] = (float)cos(a);
    g_sin[t * 64 + d] = (float)sin(a);
}

__global__ void rope_elu_k(const float* __restrict__ QKV,
                           bf16* __restrict__ Qh, bf16* __restrict__ Ql,
                           bf16* __restrict__ Kh, bf16* __restrict__ Kl)
{
    int t = blockIdx.x;
    int u = blockIdx.y;
    int d = threadIdx.x;
    int gidx, slot;
    long off;
    bf16 *oh, *ol;
    if (u < NH) { gidx = u >> 2; slot = u & 3; off = ((long)u * T_SEQ + t) * HS; oh = Qh; ol = Ql; }
    else        { gidx = u - NH; slot = 4;     off = ((long)gidx * T_SEQ + t) * HS; oh = Kh; ol = Kl; }
    const float* src = QKV + (long)t * QKVD + (gidx * 6 + slot) * HS;
    float x1 = src[d], x2 = src[d + 64];
    float cc = g_cos[t * 64 + d], ss = g_sin[t * 64 + d];
    float o1 = x1 * cc - x2 * ss;
    float o2 = x1 * ss + x2 * cc;
    float e1 = (o1 > 0.f) ? o1 + 1.f : expf(o1);
    float e2 = (o2 > 0.f) ? o2 + 1.f : expf(o2);
    bf16 h, l;
    split2(e1, h, l); oh[off + d] = h;      ol[off + d] = l;
    split2(e2, h, l); oh[off + d + 64] = h; ol[off + d + 64] = l;
}

__global__ void copy_v_k(const float* __restrict__ QKV,
                         bf16* __restrict__ Vh, bf16* __restrict__ Vl)
{
    int t = blockIdx.x, g = blockIdx.y, d = threadIdx.x;
    float v = QKV[(long)t * QKVD + (g * 6 + 5) * HS + d];
    bf16 h, l; split2(v, h, l);
    long o = ((long)g * HS + d) * T_SEQ + t;
    Vh[o] = h; Vl[o] = l;
}

// row sums of masked S (split bf16): inv[h][t] = 1/(sum_{s<=t}(Sh+Sl) + 1e-8)
__global__ void rowsum_s_k()
{
    int t = blockIdx.x, h = blockIdx.y;
    size_t base = (size_t)h * T_SEQ * T_SEQ + (size_t)t * T_SEQ;
    float sum = 0.f;
    for (int s = threadIdx.x; s <= t; s += 256)
        sum += __bfloat162float(g_Sh[base + s]) + __bfloat162float(g_Sl[base + s]);
    __shared__ float red[256];
    red[threadIdx.x] = sum; __syncthreads();
    for (int s = 128; s > 0; s >>= 1) {
        if (threadIdx.x < s) red[threadIdx.x] += red[threadIdx.x + s];
        __syncthreads();
    }
    if (threadIdx.x == 0)
        g_inv[(long)h * T_SEQ + t] = 1.f / (red[0] + 1e-8f);
}

__global__ void silu_mul_k(const float* __restrict__ H1, const float* __restrict__ H2,
                           bf16* __restrict__ Hh, bf16* __restrict__ Hl)
{
    long i = (long)blockIdx.x * 256 + threadIdx.x;
    if (i < (long)T_SEQ * INTERD) {
        float a = H1[i];
        float v = (a / (1.f + expf(-a))) * H2[i];
        bf16 h, l; split2(v, h, l);
        Hh[i] = h; Hl[i] = l;
    }
}

// ---------------- driver ----------------
static void launch_gemm_f32(const bf16* Ah, const bf16* Al, const bf16* Bh, const bf16* Bl,
                            float* C, const float* RES, int M, int N, int K,
                            int lda, int ldb, int ldc, float alpha,
                            long sA, long sB, long sC, int bdiv, int Z)
{
    gemm_bf16s<<<dim3(N / 128, M / 128, Z), 256, GEMM_SMEM>>>(
        Ah, Al, Bh, Bl, C, RES, nullptr, nullptr, nullptr, 0, 0, 0,
        K, lda, ldb, ldc, alpha, sA, sB, sC, bdiv);
}

static void launch_split(const float* X, bf16* H, bf16* L, long n)
{
    split_k<<<(int)((n + 1023) / 1024), 256>>>(X, H, L, n);
}

extern "C" void kernel_launch(void* const* d_in, const int* in_sizes, int n_in,
                              void* d_out, int out_size)
{
    const int*   idx      = (const int*)d_in[0];
    const float* wte      = (const float*)d_in[1];
    const float* attn_w   = (const float*)d_in[2];
    const float* proj_w   = (const float*)d_in[3];
    const float* w1       = (const float*)d_in[4];
    const float* w2       = (const float*)d_in[5];
    const float* w3       = (const float*)d_in[6];
    const float* norm1_w  = (const float*)d_in[7];
    const float* norm2_w  = (const float*)d_in[8];
    const float* ln_f_w   = (const float*)d_in[9];
    const float* lm_head  = (const float*)d_in[10];
    float* out = (float*)d_out;

    cudaFuncSetAttribute(gemm_bf16s, cudaFuncAttributeMaxDynamicSharedMemorySize, GEMM_SMEM);

    float *X, *QKV, *H1, *H2, *INV;
    bf16 *Nh, *Nl, *Wh, *Wl, *Qh, *Ql, *Kh, *Kl, *Vh, *Vl, *Sh, *Sl, *Yh, *Yl, *Hh, *Hl;
    cudaGetSymbolAddress((void**)&X,   g_X);
    cudaGetSymbolAddress((void**)&QKV, g_QKV);
    cudaGetSymbolAddress((void**)&H1,  g_H1);
    cudaGetSymbolAddress((void**)&H2,  g_H2);
    cudaGetSymbolAddress((void**)&INV, g_inv);
    cudaGetSymbolAddress((void**)&Nh,  g_Nh); cudaGetSymbolAddress((void**)&Nl, g_Nl);
    cudaGetSymbolAddress((void**)&Wh,  g_Wh); cudaGetSymbolAddress((void**)&Wl, g_Wl);
    cudaGetSymbolAddress((void**)&Qh,  g_Qh); cudaGetSymbolAddress((void**)&Ql, g_Ql);
    cudaGetSymbolAddress((void**)&Kh,  g_Kh); cudaGetSymbolAddress((void**)&Kl, g_Kl);
    cudaGetSymbolAddress((void**)&Vh,  g_Vh); cudaGetSymbolAddress((void**)&Vl, g_Vl);
    cudaGetSymbolAddress((void**)&Sh,  g_Sh); cudaGetSymbolAddress((void**)&Sl, g_Sl);
    cudaGetSymbolAddress((void**)&Yh,  g_Yh); cudaGetSymbolAddress((void**)&Yl, g_Yl);
    cudaGetSymbolAddress((void**)&Hh,  g_Hh); cudaGetSymbolAddress((void**)&Hl, g_Hl);

    const float scale = 1.f / sqrtf((float)HS);

    embed_k<<<T_SEQ, 256>>>(idx, wte, X);
    rope_tab_k<<<T_SEQ, 64>>>();

    for (int l = 0; l < 2; l++) {
        rmsnorm_k<<<T_SEQ, 256>>>(X, norm1_w + (long)l * NE, Nh, Nl);

        // qkv = n1 @ attn_w^T  (fp32 out)
        launch_split(attn_w + (long)l * QKVD * NE, Wh, Wl, (long)QKVD * NE);
        launch_gemm_f32(Nh, Nl, Wh, Wl, QKV, nullptr, T_SEQ, QKVD, NE,
                        NE, NE, QKVD, 1.f, 0, 0, 0, 1, 1);

        rope_elu_k<<<dim3(T_SEQ, NH + NG), 64>>>(QKV, Qh, Ql, Kh, Kl);
        copy_v_k<<<dim3(T_SEQ, NG), 128>>>(QKV, Vh, Vl);

        // S[h] = scale * Q[h] @ K[h/4]^T  -> masked split-bf16, causal block skip
        gemm_bf16s<<<dim3(T_SEQ / 128, T_SEQ / 128, NH), 256, GEMM_SMEM>>>(
            Qh, Ql, Kh, Kl, nullptr, nullptr, Sh, Sl, nullptr, 0,
            /*causal=*/1, /*limitk=*/0,
            HS, HS, HS, T_SEQ, scale,
            (long)T_SEQ * HS, (long)T_SEQ * HS, (long)T_SEQ * T_SEQ, 4);

        // inv[h][t] = 1/(rowsum + 1e-8) directly from masked split S
        rowsum_s_k<<<dim3(T_SEQ, NH), 256>>>();

        // Y[:, h*128:(h+1)*128] = inv[h] * (S[h] @ Vt[h/4]^T) -> split-bf16, K-limited
        gemm_bf16s<<<dim3(1, T_SEQ / 128, NH), 256, GEMM_SMEM>>>(
            Sh, Sl, Vh, Vl, nullptr, nullptr, Yh, Yl, INV, (long)T_SEQ,
            /*causal=*/0, /*limitk=*/1,
            T_SEQ, T_SEQ, T_SEQ, NE, 1.f,
            (long)T_SEQ * T_SEQ, (long)HS * T_SEQ, (long)HS, 4);

        // X += Y @ proj^T
        launch_split(proj_w + (long)l * NE * NE, Wh, Wl, (long)NE * NE);
        launch_gemm_f32(Yh, Yl, Wh, Wl, X, X, T_SEQ, NE, NE,
                        NE, NE, NE, 1.f, 0, 0, 0, 1, 1);

        rmsnorm_k<<<T_SEQ, 256>>>(X, norm2_w + (long)l * NE, Nh, Nl);

        launch_split(w1 + (long)l * INTERD * NE, Wh, Wl, (long)INTERD * NE);
        launch_gemm_f32(Nh, Nl, Wh, Wl, H1, nullptr, T_SEQ, INTERD, NE,
                        NE, NE, INTERD, 1.f, 0, 0, 0, 1, 1);
        launch_split(w2 + (long)l * INTERD * NE, Wh, Wl, (long)INTERD * NE);
        launch_gemm_f32(Nh, Nl, Wh, Wl, H2, nullptr, T_SEQ, INTERD, NE,
                        NE, NE, INTERD, 1.f, 0, 0, 0, 1, 1);

        silu_mul_k<<<(int)(((long)T_SEQ * INTERD + 255) / 256), 256>>>(H1, H2, Hh, Hl);

        // X += H @ w3^T
        launch_split(w3 + (long)l * NE * INTERD, Wh, Wl, (long)NE * INTERD);
        launch_gemm_f32(Hh, Hl, Wh, Wl, X, X, T_SEQ, NE, INTERD,
                        INTERD, INTERD, NE, 1.f, 0, 0, 0, 1, 1);
    }

    rmsnorm_k<<<T_SEQ, 256>>>(X, ln_f_w, Nh, Nl);

    // logits = x @ lm_head^T
    launch_split(lm_head, Wh, Wl, (long)VOCABN * NE);
    launch_gemm_f32(Nh, Nl, Wh, Wl, out, nullptr, T_SEQ, VOCABN, NE,
                    NE, NE, VOCABN, 1.f, 0, 0, 0, 1, 1);
}

// round 16
// speedup vs baseline: 1.2689x; 1.1320x over previous
#include <cuda_runtime.h>
#include <cuda_bf16.h>
#include <stdint.h>
#include <math.h>

#define T_SEQ  2048
#define NE     2048
#define NH     16
#define NG     4
#define HS     128
#define QKVD   3072
#define INTERD 5632
#define VOCABN 32000

typedef __nv_bfloat16 bf16;

// ---------------- scratch (device globals; no allocations) ----------------
__device__ __align__(256) float g_X[T_SEQ * NE];
__device__ __align__(256) float g_QKV[T_SEQ * QKVD];
__device__ __align__(256) float g_H1[T_SEQ * INTERD];
__device__ __align__(256) float g_H2[T_SEQ * INTERD];
__device__ __align__(256) float g_inv[NH * T_SEQ];

__device__ __align__(256) bf16 g_Nh[T_SEQ * NE],          g_Nl[T_SEQ * NE];
__device__ __align__(256) bf16 g_Wh[(size_t)VOCABN * NE], g_Wl[(size_t)VOCABN * NE];
__device__ __align__(256) bf16 g_Qh[NH * T_SEQ * HS],     g_Ql[NH * T_SEQ * HS];
__device__ __align__(256) bf16 g_Kh[NG * T_SEQ * HS],     g_Kl[NG * T_SEQ * HS];
__device__ __align__(256) bf16 g_Vh[NG * HS * T_SEQ],     g_Vl[NG * HS * T_SEQ];
__device__ __align__(256) bf16 g_Sh[(size_t)NH * T_SEQ * T_SEQ], g_Sl[(size_t)NH * T_SEQ * T_SEQ];
__device__ __align__(256) bf16 g_Yh[T_SEQ * NE],          g_Yl[T_SEQ * NE];
__device__ __align__(256) bf16 g_Hh[T_SEQ * INTERD],      g_Hl[T_SEQ * INTERD];

__device__ float g_cos[T_SEQ * 64];
__device__ float g_sin[T_SEQ * 64];

__device__ __forceinline__ void split2(float x, bf16& h, bf16& l) {
    h = __float2bfloat16_rn(x);
    l = __float2bfloat16_rn(x - __bfloat162float(h));
}
__device__ __forceinline__ uint32_t pack2(bf16 a, bf16 b) {
    return (uint32_t)__bfloat16_as_ushort(a) | ((uint32_t)__bfloat16_as_ushort(b) << 16);
}

#define LDSM4(R0,R1,R2,R3,ADDR) \
  asm volatile("ldmatrix.sync.aligned.m8n8.x4.shared.b16 {%0,%1,%2,%3}, [%4];" \
    : "=r"(R0),"=r"(R1),"=r"(R2),"=r"(R3) : "r"(ADDR))

#define MMA_B16(C,A,B) \
  asm volatile("mma.sync.aligned.m16n8k16.row.col.f32.bf16.bf16.f32 " \
    "{%0,%1,%2,%3},{%4,%5,%6,%7},{%8,%9},{%0,%1,%2,%3};" \
    : "+f"((C)[0]),"+f"((C)[1]),"+f"((C)[2]),"+f"((C)[3]) \
    : "r"((A)[0]),"r"((A)[1]),"r"((A)[2]),"r"((A)[3]),"r"((B)[0]),"r"((B)[1]))

__device__ __forceinline__ void cp16(bf16* s, const bf16* g) {
    uint32_t sa = (uint32_t)__cvta_generic_to_shared(s);
    asm volatile("cp.async.cg.shared.global [%0], [%1], 16;" :: "r"(sa), "l"(g));
}

// ================= WIDE kernel: 128x256 block, warp tile 64x64 =================
#define WPAD 40
#define WSA_H 0
#define WSA_L 5120
#define WSB_H 10240
#define WSB_L 20480
#define WSTAGE 30720                      // elems per stage
#define WIDE_SMEM (2 * WSTAGE * 2)        // 122880 bytes

__global__ __launch_bounds__(256, 1) void gemm_wide(
    const bf16* __restrict__ Ah, const bf16* __restrict__ Al,
    const bf16* __restrict__ Bh, const bf16* __restrict__ Bl,
    float* __restrict__ C, const float* __restrict__ RES,
    bf16* __restrict__ Ch, bf16* __restrict__ Cl,
    int causal,
    int K, int lda, int ldb, int ldc, float alpha,
    long sA, long sB, long sC, int bdiv)
{
    extern __shared__ bf16 sm[];
    int bm = blockIdx.y * 128, bn = blockIdx.x * 256;
    if (causal && bn > bm) return;

    int z = blockIdx.z;
    Ah += (long)z * sA;  Al += (long)z * sA;
    Bh += (long)(z / bdiv) * sB;  Bl += (long)(z / bdiv) * sB;
    if (C)   C   += (long)z * sC;
    if (RES) RES += (long)z * sC;
    if (Ch)  { Ch += (long)z * sC; Cl += (long)z * sC; }

    int tid = threadIdx.x;
    int lane = tid & 31, wid = tid >> 5;
    int wm = wid >> 2, wn = wid & 3;

    int a_row = wm * 64 + (lane & 15);
    int a_col = (lane >> 4) << 3;
    int b_row = wn * 64 + (lane & 7) + ((lane >> 4) << 3);
    int b_col = lane & 8;

    float c[4][8][4];
#pragma unroll
    for (int i = 0; i < 4; i++)
#pragma unroll
        for (int j = 0; j < 8; j++)
#pragma unroll
            for (int e = 0; e < 4; e++) c[i][j][e] = 0.f;

    int nk = K >> 5;

    auto prefetch = [&](int st, int k0) {
        bf16* s = sm + (st & 1) * WSTAGE;
#pragma unroll
        for (int j = 0; j < 2; j++) {        // A: 512 16B-chunks each of hi/lo
            int idx = tid + j * 256;
            int row = idx >> 2, ch = idx & 3;
            int so = row * WPAD + ch * 8;
            const bf16* gh = Ah + (long)(bm + row) * lda + k0 + ch * 8;
            const bf16* gl = Al + (long)(bm + row) * lda + k0 + ch * 8;
            cp16(s + WSA_H + so, gh);
            cp16(s + WSA_L + so, gl);
        }
#pragma unroll
        for (int j = 0; j < 4; j++) {        // B: 1024 chunks each of hi/lo
            int idx = tid + j * 256;
            int row = idx >> 2, ch = idx & 3;
            int so = row * WPAD + ch * 8;
            const bf16* gh = Bh + (long)(bn + row) * ldb + k0 + ch * 8;
            const bf16* gl = Bl + (long)(bn + row) * ldb + k0 + ch * 8;
            cp16(s + WSB_H + so, gh);
            cp16(s + WSB_L + so, gl);
        }
        asm volatile("cp.async.commit_group;");
    };

    prefetch(0, 0);

    for (int kt = 0; kt < nk; kt++) {
        if (kt + 1 < nk) {
            prefetch(kt + 1, (kt + 1) << 5);
            asm volatile("cp.async.wait_group 1;");
        } else {
            asm volatile("cp.async.wait_group 0;");
        }
        __syncthreads();

        uint32_t base = (uint32_t)__cvta_generic_to_shared(sm + (kt & 1) * WSTAGE);
#pragma unroll
        for (int ks = 0; ks < 2; ks++) {
            int kf = ks << 4;
            uint32_t ah[4][4], al[4][4];
#pragma unroll
            for (int mi = 0; mi < 4; mi++) {
                uint32_t ad = base + (uint32_t)(((a_row + mi * 16) * WPAD + kf + a_col) * 2);
                LDSM4(ah[mi][0], ah[mi][1], ah[mi][2], ah[mi][3], ad + WSA_H * 2);
                LDSM4(al[mi][0], al[mi][1], al[mi][2], al[mi][3], ad + WSA_L * 2);
            }
#pragma unroll
            for (int njp = 0; njp < 4; njp++) {   // pairs of n8 fragments
                uint32_t bd = base + (uint32_t)(((b_row + njp * 16) * WPAD + kf + b_col) * 2);
                uint32_t bh0[2], bh1[2], bl0[2], bl1[2];
                uint32_t r0, r1, r2, r3;
                LDSM4(r0, r1, r2, r3, bd + WSB_H * 2);
                bh0[0] = r0; bh0[1] = r1; bh1[0] = r2; bh1[1] = r3;
                LDSM4(r0, r1, r2, r3, bd + WSB_L * 2);
                bl0[0] = r0; bl0[1] = r1; bl1[0] = r2; bl1[1] = r3;
#pragma unroll
                for (int mi = 0; mi < 4; mi++) {
                    MMA_B16(c[mi][njp*2],   ah[mi], bh0);
                    MMA_B16(c[mi][njp*2],   ah[mi], bl0);
                    MMA_B16(c[mi][njp*2],   al[mi], bh0);
                    MMA_B16(c[mi][njp*2+1], ah[mi], bh1);
                    MMA_B16(c[mi][njp*2+1], ah[mi], bl1);
                    MMA_B16(c[mi][njp*2+1], al[mi], bh1);
                }
            }
        }
        __syncthreads();
    }

    // epilogue
    int g4 = lane >> 2, t4 = lane & 3;
#pragma unroll
    for (int mi = 0; mi < 4; mi++) {
        long r0 = bm + wm * 64 + mi * 16 + g4;
        long r1 = r0 + 8;
#pragma unroll
        for (int ni = 0; ni < 8; ni++) {
            long col = bn + wn * 64 + ni * 8 + t4 * 2;
            float v00 = c[mi][ni][0] * alpha;
            float v01 = c[mi][ni][1] * alpha;
            float v10 = c[mi][ni][2] * alpha;
            float v11 = c[mi][ni][3] * alpha;
            if (causal) {
                if (col     > r0) v00 = 0.f;
                if (col + 1 > r0) v01 = 0.f;
                if (col     > r1) v10 = 0.f;
                if (col + 1 > r1) v11 = 0.f;
            }
            if (Ch) {
                bf16 h0, l0, h1, l1;
                split2(v00, h0, l0); split2(v01, h1, l1);
                *(uint32_t*)(Ch + r0 * ldc + col) = pack2(h0, h1);
                *(uint32_t*)(Cl + r0 * ldc + col) = pack2(l0, l1);
                split2(v10, h0, l0); split2(v11, h1, l1);
                *(uint32_t*)(Ch + r1 * ldc + col) = pack2(h0, h1);
                *(uint32_t*)(Cl + r1 * ldc + col) = pack2(l0, l1);
            } else {
                float2 v0, v1;
                v0.x = v00; v0.y = v01; v1.x = v10; v1.y = v11;
                if (RES) {
                    float2 q0 = *(const float2*)(RES + r0 * ldc + col);
                    float2 q1 = *(const float2*)(RES + r1 * ldc + col);
                    v0.x += q0.x; v0.y += q0.y; v1.x += q1.x; v1.y += q1.y;
                }
                *(float2*)(C + r0 * ldc + col) = v0;
                *(float2*)(C + r1 * ldc + col) = v1;
            }
        }
    }
}

// ================= 128x128 kernel (S·V path: rowscale + K-limit) =================
#define PAD 40
#define SA_H 0
#define SA_L 5120
#define SB_H 10240
#define SB_L 15360
#define STAGE_ELEMS 20480
#define GEMM_SMEM (2 * STAGE_ELEMS * 2)

__global__ __launch_bounds__(256, 1) void gemm_bf16s(
    const bf16* __restrict__ Ah, const bf16* __restrict__ Al,
    const bf16* __restrict__ Bh, const bf16* __restrict__ Bl,
    bf16* __restrict__ Ch, bf16* __restrict__ Cl,
    const float* __restrict__ rowscale_, long sRS,
    int limitk,
    int K, int lda, int ldb, int ldc, float alpha,
    long sA, long sB, long sC, int bdiv)
{
    extern __shared__ bf16 sm[];
    int bm = blockIdx.y * 128, bn = blockIdx.x * 128;

    int z = blockIdx.z;
    Ah += (long)z * sA;  Al += (long)z * sA;
    Bh += (long)(z / bdiv) * sB;  Bl += (long)(z / bdiv) * sB;
    Ch += (long)z * sC;  Cl += (long)z * sC;
    const float* rowscale = rowscale_ ? rowscale_ + (long)z * sRS : nullptr;

    int tid = threadIdx.x;
    int lrow = tid >> 1;
    int lch  = (tid & 1) << 4;
    const bf16* gAh = Ah + (long)(bm + lrow) * lda + lch;
    const bf16* gAl = Al + (long)(bm + lrow) * lda + lch;
    const bf16* gBh = Bh + (long)(bn + lrow) * ldb + lch;
    const bf16* gBl = Bl + (long)(bn + lrow) * ldb + lch;
    int soff = lrow * PAD + lch;

    int lane = tid & 31, wid = tid >> 5;
    int wm = wid >> 2, wn = wid & 3;

    int a_row = wm * 64 + (lane & 15);
    int a_col = (lane >> 4) << 3;
    int b_row = wn * 32 + (lane & 7) + ((lane >> 4) << 3);
    int b_col = lane & 8;

    float c[4][4][4];
#pragma unroll
    for (int i = 0; i < 4; i++)
#pragma unroll
        for (int j = 0; j < 4; j++)
#pragma unroll
            for (int e = 0; e < 4; e++) c[i][j][e] = 0.f;

    int Keff = limitk ? (bm + 128 < K ? bm + 128 : K) : K;
    int nk = Keff >> 5;

    {
        bf16* s = sm + soff;
        cp16(s + SA_H, gAh); cp16(s + SA_H + 8, gAh + 8);
        cp16(s + SA_L, gAl); cp16(s + SA_L + 8, gAl + 8);
        cp16(s + SB_H, gBh); cp16(s + SB_H + 8, gBh + 8);
        cp16(s + SB_L, gBl); cp16(s + SB_L + 8, gBl + 8);
    }
    asm volatile("cp.async.commit_group;");

    for (int kt = 0; kt < nk; kt++) {
        if (kt + 1 < nk) {
            int k0 = (kt + 1) << 5;
            bf16* s = sm + ((kt + 1) & 1) * STAGE_ELEMS + soff;
            cp16(s + SA_H, gAh + k0); cp16(s + SA_H + 8, gAh + k0 + 8);
            cp16(s + SA_L, gAl + k0); cp16(s + SA_L + 8, gAl + k0 + 8);
            cp16(s + SB_H, gBh + k0); cp16(s + SB_H + 8, gBh + k0 + 8);
            cp16(s + SB_L, gBl + k0); cp16(s + SB_L + 8, gBl + k0 + 8);
            asm volatile("cp.async.commit_group;");
            asm volatile("cp.async.wait_group 1;");
        } else {
            asm volatile("cp.async.wait_group 0;");
        }
        __syncthreads();

        uint32_t base = (uint32_t)__cvta_generic_to_shared(sm + (kt & 1) * STAGE_ELEMS);
#pragma unroll
        for (int ks = 0; ks < 2; ks++) {
            int kf = ks << 4;
            uint32_t ah[4][4], al[4][4], bh[4][2], bl[4][2];
#pragma unroll
            for (int mi = 0; mi < 4; mi++) {
                uint32_t ad = base + (uint32_t)(((a_row + mi * 16) * PAD + kf + a_col) * 2);
                LDSM4(ah[mi][0], ah[mi][1], ah[mi][2], ah[mi][3], ad + SA_H * 2);
                LDSM4(al[mi][0], al[mi][1], al[mi][2], al[mi][3], ad + SA_L * 2);
            }
#pragma unroll
            for (int nj = 0; nj < 2; nj++) {
                uint32_t bd = base + (uint32_t)(((b_row + nj * 16) * PAD + kf + b_col) * 2);
                uint32_t r0, r1, r2, r3;
                LDSM4(r0, r1, r2, r3, bd + SB_H * 2);
                bh[nj*2][0] = r0; bh[nj*2][1] = r1; bh[nj*2+1][0] = r2; bh[nj*2+1][1] = r3;
                LDSM4(r0, r1, r2, r3, bd + SB_L * 2);
                bl[nj*2][0] = r0; bl[nj*2][1] = r1; bl[nj*2+1][0] = r2; bl[nj*2+1][1] = r3;
            }
#pragma unroll
            for (int mi = 0; mi < 4; mi++)
#pragma unroll
                for (int ni = 0; ni < 4; ni++) {
                    MMA_B16(c[mi][ni], ah[mi], bh[ni]);
                    MMA_B16(c[mi][ni], ah[mi], bl[ni]);
                    MMA_B16(c[mi][ni], al[mi], bh[ni]);
                }
        }
        __syncthreads();
    }

    int g4 = lane >> 2, t4 = lane & 3;
#pragma unroll
    for (int mi = 0; mi < 4; mi++) {
        long r0 = bm + wm * 64 + mi * 16 + g4;
        long r1 = r0 + 8;
        float s0 = rowscale ? rowscale[r0] : 1.f;
        float s1 = rowscale ? rowscale[r1] : 1.f;
#pragma unroll
        for (int ni = 0; ni < 4; ni++) {
            long col = bn + wn * 32 + ni * 8 + t4 * 2;
            float v00 = c[mi][ni][0] * alpha * s0;
            float v01 = c[mi][ni][1] * alpha * s0;
            float v10 = c[mi][ni][2] * alpha * s1;
            float v11 = c[mi][ni][3] * alpha * s1;
            bf16 h0, l0, h1, l1;
            split2(v00, h0, l0); split2(v01, h1, l1);
            *(uint32_t*)(Ch + r0 * ldc + col) = pack2(h0, h1);
            *(uint32_t*)(Cl + r0 * ldc + col) = pack2(l0, l1);
            split2(v10, h0, l0); split2(v11, h1, l1);
            *(uint32_t*)(Ch + r1 * ldc + col) = pack2(h0, h1);
            *(uint32_t*)(Cl + r1 * ldc + col) = pack2(l0, l1);
        }
    }
}

// ---------------- pointwise kernels ----------------
__global__ void split_k(const float* __restrict__ X, bf16* __restrict__ H,
                        bf16* __restrict__ L, long n)
{
    long i = ((long)blockIdx.x * 256 + threadIdx.x) * 4;
    if (i < n) {
        float4 v = *(const float4*)(X + i);
        bf16 h0, h1, h2, h3, l0, l1, l2, l3;
        split2(v.x, h0, l0); split2(v.y, h1, l1);
        split2(v.z, h2, l2); split2(v.w, h3, l3);
        uint2 hv; hv.x = pack2(h0, h1); hv.y = pack2(h2, h3);
        uint2 lv; lv.x = pack2(l0, l1); lv.y = pack2(l2, l3);
        *(uint2*)(H + i) = hv;
        *(uint2*)(L + i) = lv;
    }
}

__global__ void embed_k(const int* __restrict__ idx, const float* __restrict__ wte,
                        float* __restrict__ X)
{
    int t = blockIdx.x;
    int tok = idx[t];
    const float* src = wte + (long)tok * NE;
    for (int i = threadIdx.x; i < NE; i += 256)
        X[(long)t * NE + i] = src[i];
}

__global__ void rmsnorm_k(const float* __restrict__ X, const float* __restrict__ w,
                          bf16* __restrict__ H, bf16* __restrict__ L)
{
    int t = blockIdx.x;
    const float* x = X + (long)t * NE;
    float ss = 0.f;
    for (int i = threadIdx.x; i < NE; i += 256) { float v = x[i]; ss += v * v; }
    __shared__ float red[256];
    red[threadIdx.x] = ss; __syncthreads();
    for (int s = 128; s > 0; s >>= 1) {
        if (threadIdx.x < s) red[threadIdx.x] += red[threadIdx.x + s];
        __syncthreads();
    }
    float r = rsqrtf(red[0] / NE + 1e-5f);
    for (int i = threadIdx.x; i < NE; i += 256) {
        bf16 h, l; split2(x[i] * r * w[i], h, l);
        H[(long)t * NE + i] = h;
        L[(long)t * NE + i] = l;
    }
}

__global__ void rope_tab_k()
{
    int t = blockIdx.x, d = threadIdx.x;
    double theta = exp(-(double)d * (9.210340371976184 / 64.0));
    double a = (double)t * theta;
    g_cos[t * 64 + d] = (float)cos(a);
    g_sin[t * 64 + d] = (float)sin(a);
}

__global__ void rope_elu_k(const float* __restrict__ QKV,
                           bf16* __restrict__ Qh, bf16* __restrict__ Ql,
                           bf16* __restrict__ Kh, bf16* __restrict__ Kl)
{
    int t = blockIdx.x;
    int u = blockIdx.y;
    int d = threadIdx.x;
    int gidx, slot;
    long off;
    bf16 *oh, *ol;
    if (u < NH) { gidx = u >> 2; slot = u & 3; off = ((long)u * T_SEQ + t) * HS; oh = Qh; ol = Ql; }
    else        { gidx = u - NH; slot = 4;     off = ((long)gidx * T_SEQ + t) * HS; oh = Kh; ol = Kl; }
    const float* src = QKV + (long)t * QKVD + (gidx * 6 + slot) * HS;
    float x1 = src[d], x2 = src[d + 64];
    float cc = g_cos[t * 64 + d], ss = g_sin[t * 64 + d];
    float o1 = x1 * cc - x2 * ss;
    float o2 = x1 * ss + x2 * cc;
    float e1 = (o1 > 0.f) ? o1 + 1.f : expf(o1);
    float e2 = (o2 > 0.f) ? o2 + 1.f : expf(o2);
    bf16 h, l;
    split2(e1, h, l); oh[off + d] = h;      ol[off + d] = l;
    split2(e2, h, l); oh[off + d + 64] = h; ol[off + d + 64] = l;
}

__global__ void copy_v_k(const float* __restrict__ QKV,
                         bf16* __restrict__ Vh, bf16* __restrict__ Vl)
{
    int t = blockIdx.x, g = blockIdx.y, d = threadIdx.x;
    float v = QKV[(long)t * QKVD + (g * 6 + 5) * HS + d];
    bf16 h, l; split2(v, h, l);
    long o = ((long)g * HS + d) * T_SEQ + t;
    Vh[o] = h; Vl[o] = l;
}

__global__ void rowsum_s_k()
{
    int t = blockIdx.x, h = blockIdx.y;
    size_t base = (size_t)h * T_SEQ * T_SEQ + (size_t)t * T_SEQ;
    float sum = 0.f;
    for (int s = threadIdx.x; s <= t; s += 256)
        sum += __bfloat162float(g_Sh[base + s]) + __bfloat162float(g_Sl[base + s]);
    __shared__ float red[256];
    red[threadIdx.x] = sum; __syncthreads();
    for (int s = 128; s > 0; s >>= 1) {
        if (threadIdx.x < s) red[threadIdx.x] += red[threadIdx.x + s];
        __syncthreads();
    }
    if (threadIdx.x == 0)
        g_inv[(long)h * T_SEQ + t] = 1.f / (red[0] + 1e-8f);
}

__global__ void silu_mul_k(const float* __restrict__ H1, const float* __restrict__ H2,
                           bf16* __restrict__ Hh, bf16* __restrict__ Hl)
{
    long i = (long)blockIdx.x * 256 + threadIdx.x;
    if (i < (long)T_SEQ * INTERD) {
        float a = H1[i];
        float v = (a / (1.f + expf(-a))) * H2[i];
        bf16 h, l; split2(v, h, l);
        Hh[i] = h; Hl[i] = l;
    }
}

// ---------------- driver ----------------
static void launch_wide_f32(const bf16* Ah, const bf16* Al, const bf16* Bh, const bf16* Bl,
                            float* C, const float* RES, int M, int N, int K,
                            int lda, int ldb, int ldc)
{
    gemm_wide<<<dim3(N / 256, M / 128, 1), 256, WIDE_SMEM>>>(
        Ah, Al, Bh, Bl, C, RES, nullptr, nullptr, 0,
        K, lda, ldb, ldc, 1.f, 0, 0, 0, 1);
}

static void launch_split(const float* X, bf16* H, bf16* L, long n)
{
    split_k<<<(int)((n + 1023) / 1024), 256>>>(X, H, L, n);
}

extern "C" void kernel_launch(void* const* d_in, const int* in_sizes, int n_in,
                              void* d_out, int out_size)
{
    const int*   idx      = (const int*)d_in[0];
    const float* wte      = (const float*)d_in[1];
    const float* attn_w   = (const float*)d_in[2];
    const float* proj_w   = (const float*)d_in[3];
    const float* w1       = (const float*)d_in[4];
    const float* w2       = (const float*)d_in[5];
    const float* w3       = (const float*)d_in[6];
    const float* norm1_w  = (const float*)d_in[7];
    const float* norm2_w  = (const float*)d_in[8];
    const float* ln_f_w   = (const float*)d_in[9];
    const float* lm_head  = (const float*)d_in[10];
    float* out = (float*)d_out;

    cudaFuncSetAttribute(gemm_bf16s, cudaFuncAttributeMaxDynamicSharedMemorySize, GEMM_SMEM);
    cudaFuncSetAttribute(gemm_wide,  cudaFuncAttributeMaxDynamicSharedMemorySize, WIDE_SMEM);

    float *X, *QKV, *H1, *H2, *INV;
    bf16 *Nh, *Nl, *Wh, *Wl, *Qh, *Ql, *Kh, *Kl, *Vh, *Vl, *Sh, *Sl, *Yh, *Yl, *Hh, *Hl;
    cudaGetSymbolAddress((void**)&X,   g_X);
    cudaGetSymbolAddress((void**)&QKV, g_QKV);
    cudaGetSymbolAddress((void**)&H1,  g_H1);
    cudaGetSymbolAddress((void**)&H2,  g_H2);
    cudaGetSymbolAddress((void**)&INV, g_inv);
    cudaGetSymbolAddress((void**)&Nh,  g_Nh); cudaGetSymbolAddress((void**)&Nl, g_Nl);
    cudaGetSymbolAddress((void**)&Wh,  g_Wh); cudaGetSymbolAddress((void**)&Wl, g_Wl);
    cudaGetSymbolAddress((void**)&Qh,  g_Qh); cudaGetSymbolAddress((void**)&Ql, g_Ql);
    cudaGetSymbolAddress((void**)&Kh,  g_Kh); cudaGetSymbolAddress((void**)&Kl, g_Kl);
    cudaGetSymbolAddress((void**)&Vh,  g_Vh); cudaGetSymbolAddress((void**)&Vl, g_Vl);
    cudaGetSymbolAddress((void**)&Sh,  g_Sh); cudaGetSymbolAddress((void**)&Sl, g_Sl);
    cudaGetSymbolAddress((void**)&Yh,  g_Yh); cudaGetSymbolAddress((void**)&Yl, g_Yl);
    cudaGetSymbolAddress((void**)&Hh,  g_Hh); cudaGetSymbolAddress((void**)&Hl, g_Hl);

    const float scale = 1.f / sqrtf((float)HS);

    embed_k<<<T_SEQ, 256>>>(idx, wte, X);
    rope_tab_k<<<T_SEQ, 64>>>();

    for (int l = 0; l < 2; l++) {
        rmsnorm_k<<<T_SEQ, 256>>>(X, norm1_w + (long)l * NE, Nh, Nl);

        // qkv = n1 @ attn_w^T
        launch_split(attn_w + (long)l * QKVD * NE, Wh, Wl, (long)QKVD * NE);
        launch_wide_f32(Nh, Nl, Wh, Wl, QKV, nullptr, T_SEQ, QKVD, NE, NE, NE, QKVD);

        rope_elu_k<<<dim3(T_SEQ, NH + NG), 64>>>(QKV, Qh, Ql, Kh, Kl);
        copy_v_k<<<dim3(T_SEQ, NG), 128>>>(QKV, Vh, Vl);

        // S[h] = scale * Q[h] @ K[h/4]^T  -> masked split-bf16, causal skip (wide)
        gemm_wide<<<dim3(T_SEQ / 256, T_SEQ / 128, NH), 256, WIDE_SMEM>>>(
            Qh, Ql, Kh, Kl, nullptr, nullptr, Sh, Sl, /*causal=*/1,
            HS, HS, HS, T_SEQ, scale,
            (long)T_SEQ * HS, (long)T_SEQ * HS, (long)T_SEQ * T_SEQ, 4);

        rowsum_s_k<<<dim3(T_SEQ, NH), 256>>>();

        // Y = inv * (S @ Vt^T)  (128-wide kernel, K-limited)
        gemm_bf16s<<<dim3(1, T_SEQ / 128, NH), 256, GEMM_SMEM>>>(
            Sh, Sl, Vh, Vl, Yh, Yl, INV, (long)T_SEQ, /*limitk=*/1,
            T_SEQ, T_SEQ, T_SEQ, NE, 1.f,
            (long)T_SEQ * T_SEQ, (long)HS * T_SEQ, (long)HS, 4);

        // X += Y @ proj^T
        launch_split(proj_w + (long)l * NE * NE, Wh, Wl, (long)NE * NE);
        launch_wide_f32(Yh, Yl, Wh, Wl, X, X, T_SEQ, NE, NE, NE, NE, NE);

        rmsnorm_k<<<T_SEQ, 256>>>(X, norm2_w + (long)l * NE, Nh, Nl);

        launch_split(w1 + (long)l * INTERD * NE, Wh, Wl, (long)INTERD * NE);
        launch_wide_f32(Nh, Nl, Wh, Wl, H1, nullptr, T_SEQ, INTERD, NE, NE, NE, INTERD);
        launch_split(w2 + (long)l * INTERD * NE, Wh, Wl, (long)INTERD * NE);
        launch_wide_f32(Nh, Nl, Wh, Wl, H2, nullptr, T_SEQ, INTERD, NE, NE, NE, INTERD);

        silu_mul_k<<<(int)(((long)T_SEQ * INTERD + 255) / 256), 256>>>(H1, H2, Hh, Hl);

        // X += H @ w3^T
        launch_split(w3 + (long)l * NE * INTERD, Wh, Wl, (long)NE * INTERD);
        launch_wide_f32(Hh, Hl, Wh, Wl, X, X, T_SEQ, NE, INTERD, INTERD, INTERD, NE);
    }

    rmsnorm_k<<<T_SEQ, 256>>>(X, ln_f_w, Nh, Nl);

    // logits = x @ lm_head^T
    launch_split(lm_head, Wh, Wl, (long)VOCABN * NE);
    launch_wide_f32(Nh, Nl, Wh, Wl, out, nullptr, T_SEQ, VOCABN, NE, NE, NE, VOCABN);
}

// round 17
// speedup vs baseline: 1.2696x; 1.0005x over previous
#include <cuda_runtime.h>
#include <cuda_bf16.h>
#include <stdint.h>
#include <math.h>

#define T_SEQ  2048
#define NE     2048
#define NH     16
#define NG     4
#define HS     128
#define QKVD   3072
#define INTERD 5632
#define VOCABN 32000

typedef __nv_bfloat16 bf16;

// ---------------- scratch (device globals; no allocations) ----------------
__device__ __align__(256) float g_X[T_SEQ * NE];
__device__ __align__(256) float g_QKV[T_SEQ * QKVD];
__device__ __align__(256) float g_H1[T_SEQ * INTERD];
__device__ __align__(256) float g_H2[T_SEQ * INTERD];
__device__ __align__(256) float g_inv[NH * T_SEQ];

__device__ __align__(256) bf16 g_Nh[T_SEQ * NE],          g_Nl[T_SEQ * NE];
__device__ __align__(256) bf16 g_Wh[(size_t)VOCABN * NE], g_Wl[(size_t)VOCABN * NE];
__device__ __align__(256) bf16 g_Qh[NH * T_SEQ * HS],     g_Ql[NH * T_SEQ * HS];
__device__ __align__(256) bf16 g_Kh[NG * T_SEQ * HS],     g_Kl[NG * T_SEQ * HS];
__device__ __align__(256) bf16 g_Vh[NG * HS * T_SEQ],     g_Vl[NG * HS * T_SEQ];
__device__ __align__(256) bf16 g_Sh[(size_t)NH * T_SEQ * T_SEQ], g_Sl[(size_t)NH * T_SEQ * T_SEQ];
__device__ __align__(256) bf16 g_Yh[T_SEQ * NE],          g_Yl[T_SEQ * NE];
__device__ __align__(256) bf16 g_Hh[T_SEQ * INTERD],      g_Hl[T_SEQ * INTERD];

__device__ float g_cos[T_SEQ * 64];
__device__ float g_sin[T_SEQ * 64];

__device__ __forceinline__ void split2(float x, bf16& h, bf16& l) {
    h = __float2bfloat16_rn(x);
    l = __float2bfloat16_rn(x - __bfloat162float(h));
}
__device__ __forceinline__ uint32_t pack2(bf16 a, bf16 b) {
    return (uint32_t)__bfloat16_as_ushort(a) | ((uint32_t)__bfloat16_as_ushort(b) << 16);
}

#define LDSM4(R0,R1,R2,R3,ADDR) \
  asm volatile("ldmatrix.sync.aligned.m8n8.x4.shared.b16 {%0,%1,%2,%3}, [%4];" \
    : "=r"(R0),"=r"(R1),"=r"(R2),"=r"(R3) : "r"(ADDR))

#define MMA_B16(C,A,B) \
  asm volatile("mma.sync.aligned.m16n8k16.row.col.f32.bf16.bf16.f32 " \
    "{%0,%1,%2,%3},{%4,%5,%6,%7},{%8,%9},{%0,%1,%2,%3};" \
    : "+f"((C)[0]),"+f"((C)[1]),"+f"((C)[2]),"+f"((C)[3]) \
    : "r"((A)[0]),"r"((A)[1]),"r"((A)[2]),"r"((A)[3]),"r"((B)[0]),"r"((B)[1]))

__device__ __forceinline__ void cp16(bf16* s, const bf16* g) {
    uint32_t sa = (uint32_t)__cvta_generic_to_shared(s);
    asm volatile("cp.async.cg.shared.global [%0], [%1], 16;" :: "r"(sa), "l"(g));
}

// ================= WIDE kernel: 128x256 block, warp tile 64x64 =================
// Grid is M-FASTEST: bm = blockIdx.x*128, bn = blockIdx.y*256  (L2 B-reuse)
#define WPAD 40
#define WSA_H 0
#define WSA_L 5120
#define WSB_H 10240
#define WSB_L 20480
#define WSTAGE 30720                      // elems per stage
#define WIDE_SMEM (2 * WSTAGE * 2)        // 122880 bytes

__global__ __launch_bounds__(256, 1) void gemm_wide(
    const bf16* __restrict__ Ah, const bf16* __restrict__ Al,
    const bf16* __restrict__ Bh, const bf16* __restrict__ Bl,
    float* __restrict__ C, const float* __restrict__ RES,
    bf16* __restrict__ Ch, bf16* __restrict__ Cl,
    int causal,
    int K, int lda, int ldb, int ldc, float alpha,
    long sA, long sB, long sC, int bdiv)
{
    extern __shared__ bf16 sm[];
    int bm = blockIdx.x * 128, bn = blockIdx.y * 256;
    if (causal && bn > bm) return;

    int z = blockIdx.z;
    Ah += (long)z * sA;  Al += (long)z * sA;
    Bh += (long)(z / bdiv) * sB;  Bl += (long)(z / bdiv) * sB;
    if (C)   C   += (long)z * sC;
    if (RES) RES += (long)z * sC;
    if (Ch)  { Ch += (long)z * sC; Cl += (long)z * sC; }

    int tid = threadIdx.x;
    int lane = tid & 31, wid = tid >> 5;
    int wm = wid >> 2, wn = wid & 3;

    int a_row = wm * 64 + (lane & 15);
    int a_col = (lane >> 4) << 3;
    int b_row = wn * 64 + (lane & 7) + ((lane >> 4) << 3);
    int b_col = lane & 8;

    float c[4][8][4];
#pragma unroll
    for (int i = 0; i < 4; i++)
#pragma unroll
        for (int j = 0; j < 8; j++)
#pragma unroll
            for (int e = 0; e < 4; e++) c[i][j][e] = 0.f;

    int nk = K >> 5;

    auto prefetch = [&](int st, int k0) {
        bf16* s = sm + (st & 1) * WSTAGE;
#pragma unroll
        for (int j = 0; j < 2; j++) {        // A: 512 16B-chunks each of hi/lo
            int idx = tid + j * 256;
            int row = idx >> 2, ch = idx & 3;
            int so = row * WPAD + ch * 8;
            const bf16* gh = Ah + (long)(bm + row) * lda + k0 + ch * 8;
            const bf16* gl = Al + (long)(bm + row) * lda + k0 + ch * 8;
            cp16(s + WSA_H + so, gh);
            cp16(s + WSA_L + so, gl);
        }
#pragma unroll
        for (int j = 0; j < 4; j++) {        // B: 1024 chunks each of hi/lo
            int idx = tid + j * 256;
            int row = idx >> 2, ch = idx & 3;
            int so = row * WPAD + ch * 8;
            const bf16* gh = Bh + (long)(bn + row) * ldb + k0 + ch * 8;
            const bf16* gl = Bl + (long)(bn + row) * ldb + k0 + ch * 8;
            cp16(s + WSB_H + so, gh);
            cp16(s + WSB_L + so, gl);
        }
        asm volatile("cp.async.commit_group;");
    };

    prefetch(0, 0);

    for (int kt = 0; kt < nk; kt++) {
        if (kt + 1 < nk) {
            prefetch(kt + 1, (kt + 1) << 5);
            asm volatile("cp.async.wait_group 1;");
        } else {
            asm volatile("cp.async.wait_group 0;");
        }
        __syncthreads();

        uint32_t base = (uint32_t)__cvta_generic_to_shared(sm + (kt & 1) * WSTAGE);
#pragma unroll
        for (int ks = 0; ks < 2; ks++) {
            int kf = ks << 4;
            uint32_t ah[4][4], al[4][4];
#pragma unroll
            for (int mi = 0; mi < 4; mi++) {
                uint32_t ad = base + (uint32_t)(((a_row + mi * 16) * WPAD + kf + a_col) * 2);
                LDSM4(ah[mi][0], ah[mi][1], ah[mi][2], ah[mi][3], ad + WSA_H * 2);
                LDSM4(al[mi][0], al[mi][1], al[mi][2], al[mi][3], ad + WSA_L * 2);
            }
#pragma unroll
            for (int njp = 0; njp < 4; njp++) {
                uint32_t bd = base + (uint32_t)(((b_row + njp * 16) * WPAD + kf + b_col) * 2);
                uint32_t bh0[2], bh1[2], bl0[2], bl1[2];
                uint32_t r0, r1, r2, r3;
                LDSM4(r0, r1, r2, r3, bd + WSB_H * 2);
                bh0[0] = r0; bh0[1] = r1; bh1[0] = r2; bh1[1] = r3;
                LDSM4(r0, r1, r2, r3, bd + WSB_L * 2);
                bl0[0] = r0; bl0[1] = r1; bl1[0] = r2; bl1[1] = r3;
#pragma unroll
                for (int mi = 0; mi < 4; mi++) {
                    MMA_B16(c[mi][njp*2],   ah[mi], bh0);
                    MMA_B16(c[mi][njp*2],   ah[mi], bl0);
                    MMA_B16(c[mi][njp*2],   al[mi], bh0);
                    MMA_B16(c[mi][njp*2+1], ah[mi], bh1);
                    MMA_B16(c[mi][njp*2+1], ah[mi], bl1);
                    MMA_B16(c[mi][njp*2+1], al[mi], bh1);
                }
            }
        }
        __syncthreads();
    }

    // epilogue
    int g4 = lane >> 2, t4 = lane & 3;
#pragma unroll
    for (int mi = 0; mi < 4; mi++) {
        long r0 = bm + wm * 64 + mi * 16 + g4;
        long r1 = r0 + 8;
#pragma unroll
        for (int ni = 0; ni < 8; ni++) {
            long col = bn + wn * 64 + ni * 8 + t4 * 2;
            float v00 = c[mi][ni][0] * alpha;
            float v01 = c[mi][ni][1] * alpha;
            float v10 = c[mi][ni][2] * alpha;
            float v11 = c[mi][ni][3] * alpha;
            if (causal) {
                if (col     > r0) v00 = 0.f;
                if (col + 1 > r0) v01 = 0.f;
                if (col     > r1) v10 = 0.f;
                if (col + 1 > r1) v11 = 0.f;
            }
            if (Ch) {
                bf16 h0, l0, h1, l1;
                split2(v00, h0, l0); split2(v01, h1, l1);
                *(uint32_t*)(Ch + r0 * ldc + col) = pack2(h0, h1);
                *(uint32_t*)(Cl + r0 * ldc + col) = pack2(l0, l1);
                split2(v10, h0, l0); split2(v11, h1, l1);
                *(uint32_t*)(Ch + r1 * ldc + col) = pack2(h0, h1);
                *(uint32_t*)(Cl + r1 * ldc + col) = pack2(l0, l1);
            } else {
                float2 v0, v1;
                v0.x = v00; v0.y = v01; v1.x = v10; v1.y = v11;
                if (RES) {
                    float2 q0 = *(const float2*)(RES + r0 * ldc + col);
                    float2 q1 = *(const float2*)(RES + r1 * ldc + col);
                    v0.x += q0.x; v0.y += q0.y; v1.x += q1.x; v1.y += q1.y;
                }
                *(float2*)(C + r0 * ldc + col) = v0;
                *(float2*)(C + r1 * ldc + col) = v1;
            }
        }
    }
}

// ================= 128x128 kernel (S·V path: rowscale + K-limit) =================
#define PAD 40
#define SA_H 0
#define SA_L 5120
#define SB_H 10240
#define SB_L 15360
#define STAGE_ELEMS 20480
#define GEMM_SMEM (2 * STAGE_ELEMS * 2)

__global__ __launch_bounds__(256, 1) void gemm_bf16s(
    const bf16* __restrict__ Ah, const bf16* __restrict__ Al,
    const bf16* __restrict__ Bh, const bf16* __restrict__ Bl,
    bf16* __restrict__ Ch, bf16* __restrict__ Cl,
    const float* __restrict__ rowscale_, long sRS,
    int limitk,
    int K, int lda, int ldb, int ldc, float alpha,
    long sA, long sB, long sC, int bdiv)
{
    extern __shared__ bf16 sm[];
    int bm = blockIdx.y * 128, bn = blockIdx.x * 128;

    int z = blockIdx.z;
    Ah += (long)z * sA;  Al += (long)z * sA;
    Bh += (long)(z / bdiv) * sB;  Bl += (long)(z / bdiv) * sB;
    Ch += (long)z * sC;  Cl += (long)z * sC;
    const float* rowscale = rowscale_ ? rowscale_ + (long)z * sRS : nullptr;

    int tid = threadIdx.x;
    int lrow = tid >> 1;
    int lch  = (tid & 1) << 4;
    const bf16* gAh = Ah + (long)(bm + lrow) * lda + lch;
    const bf16* gAl = Al + (long)(bm + lrow) * lda + lch;
    const bf16* gBh = Bh + (long)(bn + lrow) * ldb + lch;
    const bf16* gBl = Bl + (long)(bn + lrow) * ldb + lch;
    int soff = lrow * PAD + lch;

    int lane = tid & 31, wid = tid >> 5;
    int wm = wid >> 2, wn = wid & 3;

    int a_row = wm * 64 + (lane & 15);
    int a_col = (lane >> 4) << 3;
    int b_row = wn * 32 + (lane & 7) + ((lane >> 4) << 3);
    int b_col = lane & 8;

    float c[4][4][4];
#pragma unroll
    for (int i = 0; i < 4; i++)
#pragma unroll
        for (int j = 0; j < 4; j++)
#pragma unroll
            for (int e = 0; e < 4; e++) c[i][j][e] = 0.f;

    int Keff = limitk ? (bm + 128 < K ? bm + 128 : K) : K;
    int nk = Keff >> 5;

    {
        bf16* s = sm + soff;
        cp16(s + SA_H, gAh); cp16(s + SA_H + 8, gAh + 8);
        cp16(s + SA_L, gAl); cp16(s + SA_L + 8, gAl + 8);
        cp16(s + SB_H, gBh); cp16(s + SB_H + 8, gBh + 8);
        cp16(s + SB_L, gBl); cp16(s + SB_L + 8, gBl + 8);
    }
    asm volatile("cp.async.commit_group;");

    for (int kt = 0; kt < nk; kt++) {
        if (kt + 1 < nk) {
            int k0 = (kt + 1) << 5;
            bf16* s = sm + ((kt + 1) & 1) * STAGE_ELEMS + soff;
            cp16(s + SA_H, gAh + k0); cp16(s + SA_H + 8, gAh + k0 + 8);
            cp16(s + SA_L, gAl + k0); cp16(s + SA_L + 8, gAl + k0 + 8);
            cp16(s + SB_H, gBh + k0); cp16(s + SB_H + 8, gBh + k0 + 8);
            cp16(s + SB_L, gBl + k0); cp16(s + SB_L + 8, gBl + k0 + 8);
            asm volatile("cp.async.commit_group;");
            asm volatile("cp.async.wait_group 1;");
        } else {
            asm volatile("cp.async.wait_group 0;");
        }
        __syncthreads();

        uint32_t base = (uint32_t)__cvta_generic_to_shared(sm + (kt & 1) * STAGE_ELEMS);
#pragma unroll
        for (int ks = 0; ks < 2; ks++) {
            int kf = ks << 4;
            uint32_t ah[4][4], al[4][4], bh[4][2], bl[4][2];
#pragma unroll
            for (int mi = 0; mi < 4; mi++) {
                uint32_t ad = base + (uint32_t)(((a_row + mi * 16) * PAD + kf + a_col) * 2);
                LDSM4(ah[mi][0], ah[mi][1], ah[mi][2], ah[mi][3], ad + SA_H * 2);
                LDSM4(al[mi][0], al[mi][1], al[mi][2], al[mi][3], ad + SA_L * 2);
            }
#pragma unroll
            for (int nj = 0; nj < 2; nj++) {
                uint32_t bd = base + (uint32_t)(((b_row + nj * 16) * PAD + kf + b_col) * 2);
                uint32_t r0, r1, r2, r3;
                LDSM4(r0, r1, r2, r3, bd + SB_H * 2);
                bh[nj*2][0] = r0; bh[nj*2][1] = r1; bh[nj*2+1][0] = r2; bh[nj*2+1][1] = r3;
                LDSM4(r0, r1, r2, r3, bd + SB_L * 2);
                bl[nj*2][0] = r0; bl[nj*2][1] = r1; bl[nj*2+1][0] = r2; bl[nj*2+1][1] = r3;
            }
#pragma unroll
            for (int mi = 0; mi < 4; mi++)
#pragma unroll
                for (int ni = 0; ni < 4; ni++) {
                    MMA_B16(c[mi][ni], ah[mi], bh[ni]);
                    MMA_B16(c[mi][ni], ah[mi], bl[ni]);
                    MMA_B16(c[mi][ni], al[mi], bh[ni]);
                }
        }
        __syncthreads();
    }

    int g4 = lane >> 2, t4 = lane & 3;
#pragma unroll
    for (int mi = 0; mi < 4; mi++) {
        long r0 = bm + wm * 64 + mi * 16 + g4;
        long r1 = r0 + 8;
        float s0 = rowscale ? rowscale[r0] : 1.f;
        float s1 = rowscale ? rowscale[r1] : 1.f;
#pragma unroll
        for (int ni = 0; ni < 4; ni++) {
            long col = bn + wn * 32 + ni * 8 + t4 * 2;
            float v00 = c[mi][ni][0] * alpha * s0;
            float v01 = c[mi][ni][1] * alpha * s0;
            float v10 = c[mi][ni][2] * alpha * s1;
            float v11 = c[mi][ni][3] * alpha * s1;
            bf16 h0, l0, h1, l1;
            split2(v00, h0, l0); split2(v01, h1, l1);
            *(uint32_t*)(Ch + r0 * ldc + col) = pack2(h0, h1);
            *(uint32_t*)(Cl + r0 * ldc + col) = pack2(l0, l1);
            split2(v10, h0, l0); split2(v11, h1, l1);
            *(uint32_t*)(Ch + r1 * ldc + col) = pack2(h0, h1);
            *(uint32_t*)(Cl + r1 * ldc + col) = pack2(l0, l1);
        }
    }
}

// ---------------- pointwise kernels ----------------
// 4x unrolled split: each thread does 4 independent float4 loads (MLP=4)
__global__ void split_k(const float* __restrict__ X, bf16* __restrict__ H,
                        bf16* __restrict__ L, long n)
{
    long base = (long)blockIdx.x * 4096 + threadIdx.x * 4;
    float4 v[4];
#pragma unroll
    for (int j = 0; j < 4; j++) {
        long i = base + (long)j * 1024;
        if (i < n) v[j] = *(const float4*)(X + i);
    }
#pragma unroll
    for (int j = 0; j < 4; j++) {
        long i = base + (long)j * 1024;
        if (i < n) {
            bf16 h0, h1, h2, h3, l0, l1, l2, l3;
            split2(v[j].x, h0, l0); split2(v[j].y, h1, l1);
            split2(v[j].z, h2, l2); split2(v[j].w, h3, l3);
            uint2 hv; hv.x = pack2(h0, h1); hv.y = pack2(h2, h3);
            uint2 lv; lv.x = pack2(l0, l1); lv.y = pack2(l2, l3);
            *(uint2*)(H + i) = hv;
            *(uint2*)(L + i) = lv;
        }
    }
}

__global__ void embed_k(const int* __restrict__ idx, const float* __restrict__ wte,
                        float* __restrict__ X)
{
    int t = blockIdx.x;
    int tok = idx[t];
    const float* src = wte + (long)tok * NE;
    for (int i = threadIdx.x; i < NE; i += 256)
        X[(long)t * NE + i] = src[i];
}

__global__ void rmsnorm_k(const float* __restrict__ X, const float* __restrict__ w,
                          bf16* __restrict__ H, bf16* __restrict__ L)
{
    int t = blockIdx.x;
    const float* x = X + (long)t * NE;
    float ss = 0.f;
    for (int i = threadIdx.x; i < NE; i += 256) { float v = x[i]; ss += v * v; }
    __shared__ float red[256];
    red[threadIdx.x] = ss; __syncthreads();
    for (int s = 128; s > 0; s >>= 1) {
        if (threadIdx.x < s) red[threadIdx.x] += red[threadIdx.x + s];
        __syncthreads();
    }
    float r = rsqrtf(red[0] / NE + 1e-5f);
    for (int i = threadIdx.x; i < NE; i += 256) {
        bf16 h, l; split2(x[i] * r * w[i], h, l);
        H[(long)t * NE + i] = h;
        L[(long)t * NE + i] = l;
    }
}

__global__ void rope_tab_k()
{
    int t = blockIdx.x, d = threadIdx.x;
    double theta = exp(-(double)d * (9.210340371976184 / 64.0));
    double a = (double)t * theta;
    g_cos[t * 64 + d] = (float)cos(a);
    g_sin[t * 64 + d] = (float)sin(a);
}

__global__ void rope_elu_k(const float* __restrict__ QKV,
                           bf16* __restrict__ Qh, bf16* __restrict__ Ql,
                           bf16* __restrict__ Kh, bf16* __restrict__ Kl)
{
    int t = blockIdx.x;
    int u = blockIdx.y;
    int d = threadIdx.x;
    int gidx, slot;
    long off;
    bf16 *oh, *ol;
    if (u < NH) { gidx = u >> 2; slot = u & 3; off = ((long)u * T_SEQ + t) * HS; oh = Qh; ol = Ql; }
    else        { gidx = u - NH; slot = 4;     off = ((long)gidx * T_SEQ + t) * HS; oh = Kh; ol = Kl; }
    const float* src = QKV + (long)t * QKVD + (gidx * 6 + slot) * HS;
    float x1 = src[d], x2 = src[d + 64];
    float cc = g_cos[t * 64 + d], ss = g_sin[t * 64 + d];
    float o1 = x1 * cc - x2 * ss;
    float o2 = x1 * ss + x2 * cc;
    float e1 = (o1 > 0.f) ? o1 + 1.f : expf(o1);
    float e2 = (o2 > 0.f) ? o2 + 1.f : expf(o2);
    bf16 h, l;
    split2(e1, h, l); oh[off + d] = h;      ol[off + d] = l;
    split2(e2, h, l); oh[off + d + 64] = h; ol[off + d + 64] = l;
}

__global__ void copy_v_k(const float* __restrict__ QKV,
                         bf16* __restrict__ Vh, bf16* __restrict__ Vl)
{
    int t = blockIdx.x, g = blockIdx.y, d = threadIdx.x;
    float v = QKV[(long)t * QKVD + (g * 6 + 5) * HS + d];
    bf16 h, l; split2(v, h, l);
    long o = ((long)g * HS + d) * T_SEQ + t;
    Vh[o] = h; Vl[o] = l;
}

__global__ void rowsum_s_k()
{
    int t = blockIdx.x, h = blockIdx.y;
    size_t base = (size_t)h * T_SEQ * T_SEQ + (size_t)t * T_SEQ;
    float sum = 0.f;
    for (int s = threadIdx.x; s <= t; s += 256)
        sum += __bfloat162float(g_Sh[base + s]) + __bfloat162float(g_Sl[base + s]);
    __shared__ float red[256];
    red[threadIdx.x] = sum; __syncthreads();
    for (int s = 128; s > 0; s >>= 1) {
        if (threadIdx.x < s) red[threadIdx.x] += red[threadIdx.x + s];
        __syncthreads();
    }
    if (threadIdx.x == 0)
        g_inv[(long)h * T_SEQ + t] = 1.f / (red[0] + 1e-8f);
}

__global__ void silu_mul_k(const float* __restrict__ H1, const float* __restrict__ H2,
                           bf16* __restrict__ Hh, bf16* __restrict__ Hl)
{
    long i = (long)blockIdx.x * 256 + threadIdx.x;
    if (i < (long)T_SEQ * INTERD) {
        float a = H1[i];
        float v = (a / (1.f + expf(-a))) * H2[i];
        bf16 h, l; split2(v, h, l);
        Hh[i] = h; Hl[i] = l;
    }
}

// ---------------- driver ----------------
static void launch_wide_f32(const bf16* Ah, const bf16* Al, const bf16* Bh, const bf16* Bl,
                            float* C, const float* RES, int M, int N, int K,
                            int lda, int ldb, int ldc)
{
    gemm_wide<<<dim3(M / 128, N / 256, 1), 256, WIDE_SMEM>>>(
        Ah, Al, Bh, Bl, C, RES, nullptr, nullptr, 0,
        K, lda, ldb, ldc, 1.f, 0, 0, 0, 1);
}

static void launch_split(const float* X, bf16* H, bf16* L, long n)
{
    split_k<<<(int)((n + 4095) / 4096), 256>>>(X, H, L, n);
}

extern "C" void kernel_launch(void* const* d_in, const int* in_sizes, int n_in,
                              void* d_out, int out_size)
{
    const int*   idx      = (const int*)d_in[0];
    const float* wte      = (const float*)d_in[1];
    const float* attn_w   = (const float*)d_in[2];
    const float* proj_w   = (const float*)d_in[3];
    const float* w1       = (const float*)d_in[4];
    const float* w2       = (const float*)d_in[5];
    const float* w3       = (const float*)d_in[6];
    const float* norm1_w  = (const float*)d_in[7];
    const float* norm2_w  = (const float*)d_in[8];
    const float* ln_f_w   = (const float*)d_in[9];
    const float* lm_head  = (const float*)d_in[10];
    float* out = (float*)d_out;

    cudaFuncSetAttribute(gemm_bf16s, cudaFuncAttributeMaxDynamicSharedMemorySize, GEMM_SMEM);
    cudaFuncSetAttribute(gemm_wide,  cudaFuncAttributeMaxDynamicSharedMemorySize, WIDE_SMEM);

    float *X, *QKV, *H1, *H2, *INV;
    bf16 *Nh, *Nl, *Wh, *Wl, *Qh, *Ql, *Kh, *Kl, *Vh, *Vl, *Sh, *Sl, *Yh, *Yl, *Hh, *Hl;
    cudaGetSymbolAddress((void**)&X,   g_X);
    cudaGetSymbolAddress((void**)&QKV, g_QKV);
    cudaGetSymbolAddress((void**)&H1,  g_H1);
    cudaGetSymbolAddress((void**)&H2,  g_H2);
    cudaGetSymbolAddress((void**)&INV, g_inv);
    cudaGetSymbolAddress((void**)&Nh,  g_Nh); cudaGetSymbolAddress((void**)&Nl, g_Nl);
    cudaGetSymbolAddress((void**)&Wh,  g_Wh); cudaGetSymbolAddress((void**)&Wl, g_Wl);
    cudaGetSymbolAddress((void**)&Qh,  g_Qh); cudaGetSymbolAddress((void**)&Ql, g_Ql);
    cudaGetSymbolAddress((void**)&Kh,  g_Kh); cudaGetSymbolAddress((void**)&Kl, g_Kl);
    cudaGetSymbolAddress((void**)&Vh,  g_Vh); cudaGetSymbolAddress((void**)&Vl, g_Vl);
    cudaGetSymbolAddress((void**)&Sh,  g_Sh); cudaGetSymbolAddress((void**)&Sl, g_Sl);
    cudaGetSymbolAddress((void**)&Yh,  g_Yh); cudaGetSymbolAddress((void**)&Yl, g_Yl);
    cudaGetSymbolAddress((void**)&Hh,  g_Hh); cudaGetSymbolAddress((void**)&Hl, g_Hl);

    const float scale = 1.f / sqrtf((float)HS);

    embed_k<<<T_SEQ, 256>>>(idx, wte, X);
    rope_tab_k<<<T_SEQ, 64>>>();

    for (int l = 0; l < 2; l++) {
        rmsnorm_k<<<T_SEQ, 256>>>(X, norm1_w + (long)l * NE, Nh, Nl);

        // qkv = n1 @ attn_w^T
        launch_split(attn_w + (long)l * QKVD * NE, Wh, Wl, (long)QKVD * NE);
        launch_wide_f32(Nh, Nl, Wh, Wl, QKV, nullptr, T_SEQ, QKVD, NE, NE, NE, QKVD);

        rope_elu_k<<<dim3(T_SEQ, NH + NG), 64>>>(QKV, Qh, Ql, Kh, Kl);
        copy_v_k<<<dim3(T_SEQ, NG), 128>>>(QKV, Vh, Vl);

        // S[h] = scale * Q[h] @ K[h/4]^T  -> masked split-bf16, causal skip (wide)
        gemm_wide<<<dim3(T_SEQ / 128, T_SEQ / 256, NH), 256, WIDE_SMEM>>>(
            Qh, Ql, Kh, Kl, nullptr, nullptr, Sh, Sl, /*causal=*/1,
            HS, HS, HS, T_SEQ, scale,
            (long)T_SEQ * HS, (long)T_SEQ * HS, (long)T_SEQ * T_SEQ, 4);

        rowsum_s_k<<<dim3(T_SEQ, NH), 256>>>();

        // Y = inv * (S @ Vt^T)  (128-wide kernel, K-limited)
        gemm_bf16s<<<dim3(1, T_SEQ / 128, NH), 256, GEMM_SMEM>>>(
            Sh, Sl, Vh, Vl, Yh, Yl, INV, (long)T_SEQ, /*limitk=*/1,
            T_SEQ, T_SEQ, T_SEQ, NE, 1.f,
            (long)T_SEQ * T_SEQ, (long)HS * T_SEQ, (long)HS, 4);

        // X += Y @ proj^T
        launch_split(proj_w + (long)l * NE * NE, Wh, Wl, (long)NE * NE);
        launch_wide_f32(Yh, Yl, Wh, Wl, X, X, T_SEQ, NE, NE, NE, NE, NE);

        rmsnorm_k<<<T_SEQ, 256>>>(X, norm2_w + (long)l * NE, Nh, Nl);

        launch_split(w1 + (long)l * INTERD * NE, Wh, Wl, (long)INTERD * NE);
        launch_wide_f32(Nh, Nl, Wh, Wl, H1, nullptr, T_SEQ, INTERD, NE, NE, NE, INTERD);
        launch_split(w2 + (long)l * INTERD * NE, Wh, Wl, (long)INTERD * NE);
        launch_wide_f32(Nh, Nl, Wh, Wl, H2, nullptr, T_SEQ, INTERD, NE, NE, NE, INTERD);

        silu_mul_k<<<(int)(((long)T_SEQ * INTERD + 255) / 256), 256>>>(H1, H2, Hh, Hl);

        // X += H @ w3^T
        launch_split(w3 + (long)l * NE * INTERD, Wh, Wl, (long)NE * INTERD);
        launch_wide_f32(Hh, Hl, Wh, Wl, X, X, T_SEQ, NE, INTERD, INTERD, INTERD, NE);
    }

    rmsnorm_k<<<T_SEQ, 256>>>(X, ln_f_w, Nh, Nl);

    // logits = x @ lm_head^T
    launch_split(lm_head, Wh, Wl, (long)VOCABN * NE);
    launch_wide_f32(Nh, Nl, Wh, Wl, out, nullptr, T_SEQ, VOCABN, NE, NE, NE, VOCABN);
}